// round 2
// baseline (speedup 1.0000x reference)
#include <cuda_runtime.h>
#include <math.h>

// ----------------------------------------------------------------------------
// Problem constants (B=16, N=M=1024, DIM=768, 2 heads)
// ----------------------------------------------------------------------------
#define BATCH 16
#define SEQ   1024
#define DIM   768
#define XU_ELEMS (16LL*1024*768)        // 12,582,912

// ----------------------------------------------------------------------------
// Scratch (static device globals — allocation-free)
// ----------------------------------------------------------------------------
__device__ float g_xu  [16LL*1024*768];          // x @ U^T            (50 MB)
__device__ float g_xs  [2LL*16*1024*768];        // x1, x2             (100 MB)
__device__ float g_attn[2LL*16*1024*1024];       // scores -> attn [B,2,N,M] (134 MB)
__device__ float g_pos [1024LL*1024];            // pos_score [N,M]    (4 MB)
__device__ float g_ent [16*2*1024];              // entropy [B,2,N]
__device__ int   g_sel [16*1024];                // routed head per (b,n)

// ----------------------------------------------------------------------------
// Block reductions (256 threads, 8 warps)
// ----------------------------------------------------------------------------
__device__ __forceinline__ float block_sum(float v, float* red) {
    #pragma unroll
    for (int o = 16; o; o >>= 1) v += __shfl_xor_sync(0xffffffffu, v, o);
    __syncthreads();                       // protect red from previous use
    if ((threadIdx.x & 31) == 0) red[threadIdx.x >> 5] = v;
    __syncthreads();
    float r = red[0];
    #pragma unroll
    for (int w = 1; w < 8; w++) r += red[w];
    return r;
}

__device__ __forceinline__ float block_max(float v, float* red) {
    #pragma unroll
    for (int o = 16; o; o >>= 1) v = fmaxf(v, __shfl_xor_sync(0xffffffffu, v, o));
    __syncthreads();
    if ((threadIdx.x & 31) == 0) red[threadIdx.x >> 5] = v;
    __syncthreads();
    float r = red[0];
    #pragma unroll
    for (int w = 1; w < 8; w++) r = fmaxf(r, red[w]);
    return r;
}

// ----------------------------------------------------------------------------
// SGEMM NT: C[i,j] = alpha * sum_k A[i,k] * B[j,k]
// A: [M,K] rm, B: [N,K] rm, C: [M,N] rm. M,N mult of 128, K mult of 8.
// 128x128 tile, 256 threads, 8x8 per thread.
// ----------------------------------------------------------------------------
__global__ __launch_bounds__(256, 2)
void sgemm_nt(const float* __restrict__ Ab, const float* __restrict__ Bb,
              float* __restrict__ Cb, int M, int N, int K, float alpha,
              long sA, long sB, long sC)
{
    const float* A = Ab + (long)blockIdx.z * sA;
    const float* Bp = Bb + (long)blockIdx.z * sB;
    float*       C = Cb + (long)blockIdx.z * sC;

    __shared__ float As[8][128];
    __shared__ float Bs[8][128];

    const int tid  = threadIdx.x;
    const int tx   = tid & 15;
    const int ty   = tid >> 4;
    const int row0 = blockIdx.y * 128;
    const int col0 = blockIdx.x * 128;

    const int lm = tid >> 1;
    const int lk = (tid & 1) * 4;
    const float* Aload = A + (long)(row0 + lm) * K + lk;
    const float* Bload = Bp + (long)(col0 + lm) * K + lk;

    float acc[8][8] = {};

    for (int k0 = 0; k0 < K; k0 += 8) {
        float4 av = *(const float4*)(Aload + k0);
        float4 bv = *(const float4*)(Bload + k0);
        __syncthreads();
        As[lk+0][lm] = av.x; As[lk+1][lm] = av.y; As[lk+2][lm] = av.z; As[lk+3][lm] = av.w;
        Bs[lk+0][lm] = bv.x; Bs[lk+1][lm] = bv.y; Bs[lk+2][lm] = bv.z; Bs[lk+3][lm] = bv.w;
        __syncthreads();
        #pragma unroll
        for (int kk = 0; kk < 8; kk++) {
            float4 a0 = *(const float4*)&As[kk][ty*4];
            float4 a1 = *(const float4*)&As[kk][64 + ty*4];
            float4 b0 = *(const float4*)&Bs[kk][tx*4];
            float4 b1 = *(const float4*)&Bs[kk][64 + tx*4];
            float ar[8] = {a0.x,a0.y,a0.z,a0.w,a1.x,a1.y,a1.z,a1.w};
            float br[8] = {b0.x,b0.y,b0.z,b0.w,b1.x,b1.y,b1.z,b1.w};
            #pragma unroll
            for (int i = 0; i < 8; i++)
                #pragma unroll
                for (int j = 0; j < 8; j++)
                    acc[i][j] += ar[i] * br[j];
        }
    }

    #pragma unroll
    for (int i = 0; i < 8; i++) {
        int r = row0 + ((i < 4) ? (ty*4 + i) : (64 + ty*4 + i - 4));
        float* cr = C + (long)r * N + col0;
        float4 o0 = make_float4(acc[i][0]*alpha, acc[i][1]*alpha, acc[i][2]*alpha, acc[i][3]*alpha);
        float4 o1 = make_float4(acc[i][4]*alpha, acc[i][5]*alpha, acc[i][6]*alpha, acc[i][7]*alpha);
        *(float4*)(cr + tx*4)      = o0;
        *(float4*)(cr + 64 + tx*4) = o1;
    }
}

// ----------------------------------------------------------------------------
// SGEMM NN with per-k scaling: C[i,j] = sum_k A[i,k]*Sv[k]^2*B[k,j]
// A: [M,K] rm, B: [K,N] rm, Sv: [K].
// ----------------------------------------------------------------------------
__global__ __launch_bounds__(256, 2)
void sgemm_nn_scaled(const float* __restrict__ A, const float* __restrict__ Bp,
                     const float* __restrict__ Sv, float* __restrict__ C,
                     int M, int N, int K)
{
    __shared__ float As[8][128];
    __shared__ float Bs[8][128];

    const int tid  = threadIdx.x;
    const int tx   = tid & 15;
    const int ty   = tid >> 4;
    const int row0 = blockIdx.y * 128;
    const int col0 = blockIdx.x * 128;

    const int lmA = tid >> 1;
    const int lkA = (tid & 1) * 4;
    const int lnB = (tid & 31) * 4;
    const int lkB = tid >> 5;

    const float* Aload = A + (long)(row0 + lmA) * K + lkA;
    const float* Bload = Bp + (long)lkB * N + col0 + lnB;

    float acc[8][8] = {};

    for (int k0 = 0; k0 < K; k0 += 8) {
        float4 av = *(const float4*)(Aload + k0);
        float4 sv = *(const float4*)(Sv + k0 + lkA);
        av.x *= sv.x * sv.x; av.y *= sv.y * sv.y;
        av.z *= sv.z * sv.z; av.w *= sv.w * sv.w;
        float4 bv = *(const float4*)(Bload + (long)k0 * N);
        __syncthreads();
        As[lkA+0][lmA] = av.x; As[lkA+1][lmA] = av.y; As[lkA+2][lmA] = av.z; As[lkA+3][lmA] = av.w;
        *(float4*)&Bs[lkB][lnB] = bv;
        __syncthreads();
        #pragma unroll
        for (int kk = 0; kk < 8; kk++) {
            float4 a0 = *(const float4*)&As[kk][ty*4];
            float4 a1 = *(const float4*)&As[kk][64 + ty*4];
            float4 b0 = *(const float4*)&Bs[kk][tx*4];
            float4 b1 = *(const float4*)&Bs[kk][64 + tx*4];
            float ar[8] = {a0.x,a0.y,a0.z,a0.w,a1.x,a1.y,a1.z,a1.w};
            float br[8] = {b0.x,b0.y,b0.z,b0.w,b1.x,b1.y,b1.z,b1.w};
            #pragma unroll
            for (int i = 0; i < 8; i++)
                #pragma unroll
                for (int j = 0; j < 8; j++)
                    acc[i][j] += ar[i] * br[j];
        }
    }

    #pragma unroll
    for (int i = 0; i < 8; i++) {
        int r = row0 + ((i < 4) ? (ty*4 + i) : (64 + ty*4 + i - 4));
        float* cr = C + (long)r * N + col0;
        *(float4*)(cr + tx*4)      = make_float4(acc[i][0], acc[i][1], acc[i][2], acc[i][3]);
        *(float4*)(cr + 64 + tx*4) = make_float4(acc[i][4], acc[i][5], acc[i][6], acc[i][7]);
    }
}

// ----------------------------------------------------------------------------
// Gathered AV GEMM: out[b,n,d] = sum_m attn[b, sel[b,n], n, m] * y[b,m,d]
// A rows gathered from [B,2,N,M]; B = y[b]: [M=1024, D=768] rm. K=1024.
// ----------------------------------------------------------------------------
__global__ __launch_bounds__(256, 2)
void sgemm_av_gather(const float* __restrict__ attn, const float* __restrict__ y,
                     const int* __restrict__ sel, float* __restrict__ out)
{
    const int b    = blockIdx.z;
    const int row0 = blockIdx.y * 128;
    const int col0 = blockIdx.x * 128;

    __shared__ float As[8][128];
    __shared__ float Bs[8][128];

    const int tid = threadIdx.x;
    const int tx  = tid & 15;
    const int ty  = tid >> 4;

    const int lmA = tid >> 1;
    const int lkA = (tid & 1) * 4;
    const int lnB = (tid & 31) * 4;
    const int lkB = tid >> 5;

    const int n = row0 + lmA;
    const int s = sel[b * SEQ + n];
    const float* Aload = attn + ((long)(b * 2 + s) * SEQ + n) * SEQ + lkA;
    const float* Bload = y + (long)b * SEQ * DIM + (long)lkB * DIM + col0 + lnB;

    float acc[8][8] = {};

    for (int k0 = 0; k0 < SEQ; k0 += 8) {
        float4 av = *(const float4*)(Aload + k0);
        float4 bv = *(const float4*)(Bload + (long)k0 * DIM);
        __syncthreads();
        As[lkA+0][lmA] = av.x; As[lkA+1][lmA] = av.y; As[lkA+2][lmA] = av.z; As[lkA+3][lmA] = av.w;
        *(float4*)&Bs[lkB][lnB] = bv;
        __syncthreads();
        #pragma unroll
        for (int kk = 0; kk < 8; kk++) {
            float4 a0 = *(const float4*)&As[kk][ty*4];
            float4 a1 = *(const float4*)&As[kk][64 + ty*4];
            float4 b0 = *(const float4*)&Bs[kk][tx*4];
            float4 b1 = *(const float4*)&Bs[kk][64 + tx*4];
            float ar[8] = {a0.x,a0.y,a0.z,a0.w,a1.x,a1.y,a1.z,a1.w};
            float br[8] = {b0.x,b0.y,b0.z,b0.w,b1.x,b1.y,b1.z,b1.w};
            #pragma unroll
            for (int i = 0; i < 8; i++)
                #pragma unroll
                for (int j = 0; j < 8; j++)
                    acc[i][j] += ar[i] * br[j];
        }
    }

    #pragma unroll
    for (int i = 0; i < 8; i++) {
        int r = row0 + ((i < 4) ? (ty*4 + i) : (64 + ty*4 + i - 4));
        float* cr = out + ((long)b * SEQ + r) * DIM + col0;
        *(float4*)(cr + tx*4)      = make_float4(acc[i][0], acc[i][1], acc[i][2], acc[i][3]);
        *(float4*)(cr + 64 + tx*4) = make_float4(acc[i][4], acc[i][5], acc[i][6], acc[i][7]);
    }
}

// ----------------------------------------------------------------------------
// pos_score: pos[n,m] = softmax_m( sum_c coords[n,m,c] * pos_emb[n,c] )
// One block per n (256 threads x 4 elems).
// ----------------------------------------------------------------------------
__global__ void pos_softmax(const float* __restrict__ coords, const float* __restrict__ pe,
                            float* __restrict__ pos)
{
    const int n   = blockIdx.x;
    const int tid = threadIdx.x;
    __shared__ float red[8];
    __shared__ float w[6];
    if (tid < 6) w[tid] = pe[n * 6 + tid];
    __syncthreads();

    float p[4];
    #pragma unroll
    for (int i = 0; i < 4; i++) {
        const float* c = coords + ((long)n * SEQ + tid * 4 + i) * 6;
        p[i] = w[0]*c[0] + w[1]*c[1] + w[2]*c[2] + w[3]*c[3] + w[4]*c[4] + w[5]*c[5];
    }
    float mx = fmaxf(fmaxf(p[0], p[1]), fmaxf(p[2], p[3]));
    mx = block_max(mx, red);
    float e[4], sum = 0.f;
    #pragma unroll
    for (int i = 0; i < 4; i++) { e[i] = expf(p[i] - mx); sum += e[i]; }
    sum = block_sum(sum, red);
    float inv = 1.f / sum;
    float* dst = pos + (long)n * SEQ + tid * 4;
    *(float4*)dst = make_float4(e[0]*inv, e[1]*inv, e[2]*inv, e[3]*inv);
}

// ----------------------------------------------------------------------------
// Fused softmax + gating mixture + entropy, in place on g_attn.
// One block per row r = (b*2+h)*N + n. attn = (1-g)*softmax(s) + g*pos[n].
// ----------------------------------------------------------------------------
__global__ void softmax_mix(float* __restrict__ attn, const float* __restrict__ pos,
                            float* __restrict__ ent, const float* __restrict__ gating)
{
    const long r  = blockIdx.x;
    const int  n  = (int)(r & (SEQ - 1));
    const int tid = threadIdx.x;
    __shared__ float red[8];

    float* row = attn + r * SEQ;
    const float* q = pos + (long)n * SEQ;

    float4 v = *(const float4*)(row + tid * 4);
    float mx = fmaxf(fmaxf(v.x, v.y), fmaxf(v.z, v.w));
    mx = block_max(mx, red);

    float4 e;
    e.x = expf(v.x - mx); e.y = expf(v.y - mx);
    e.z = expf(v.z - mx); e.w = expf(v.w - mx);
    float sum = e.x + e.y + e.z + e.w;
    sum = block_sum(sum, red);

    float g   = 1.f / (1.f + expf(-gating[0]));
    float omg = (1.f - g) / sum;
    float4 qv = *(const float4*)(q + tid * 4);
    float4 a;
    a.x = omg*e.x + g*qv.x; a.y = omg*e.y + g*qv.y;
    a.z = omg*e.z + g*qv.z; a.w = omg*e.w + g*qv.w;

    float ep = -(a.x * logf(a.x + 1e-8f) + a.y * logf(a.y + 1e-8f)
               + a.z * logf(a.z + 1e-8f) + a.w * logf(a.w + 1e-8f));
    ep = block_sum(ep, red);

    *(float4*)(row + tid * 4) = a;
    if (tid == 0) ent[r] = ep;
}

// ----------------------------------------------------------------------------
// Entropy routing: pick head with larger hmap (h = 2 - 2*sigmoid(temp*ent)).
// Writes heat_map to d_out tail and sel for the AV gather.
// ----------------------------------------------------------------------------
__global__ void route_kernel(const float* __restrict__ ent, const float* __restrict__ temp,
                             int* __restrict__ sel, float* __restrict__ heat)
{
    const int i = blockIdx.x * blockDim.x + threadIdx.x;
    if (i >= BATCH * SEQ) return;
    const int b = i >> 10, n = i & 1023;
    const float t  = temp[0];
    const float e0 = ent[b * 2048 + n];
    const float e1 = ent[b * 2048 + 1024 + n];
    const float h0 = 2.f - 2.f / (1.f + expf(-t * e0));
    const float h1 = 2.f - 2.f / (1.f + expf(-t * e1));
    const int s = (h0 >= h1) ? 0 : 1;
    sel[i]  = s;
    heat[i] = s ? h1 : h0;
}

// ----------------------------------------------------------------------------
// kernel_launch
// Inputs: 0:x 1:y 2:coords 3:U 4:S1 5:S2 6:gating 7:temp 8:pos_emb
// Output: out [B,N,DIM] (12,582,912 floats) then heat_map [B,N,1] (16,384).
// ----------------------------------------------------------------------------
extern "C" void kernel_launch(void* const* d_in, const int* in_sizes, int n_in,
                              void* d_out, int out_size)
{
    const float* x      = (const float*)d_in[0];
    const float* y      = (const float*)d_in[1];
    const float* coords = (const float*)d_in[2];
    const float* U      = (const float*)d_in[3];
    const float* S1     = (const float*)d_in[4];
    const float* S2     = (const float*)d_in[5];
    const float* gating = (const float*)d_in[6];
    const float* temp   = (const float*)d_in[7];
    const float* pe     = (const float*)d_in[8];
    float* out = (float*)d_out;

    float *xu, *xs, *attn, *pos, *ent; int* sel;
    cudaGetSymbolAddress((void**)&xu,   g_xu);
    cudaGetSymbolAddress((void**)&xs,   g_xs);
    cudaGetSymbolAddress((void**)&attn, g_attn);
    cudaGetSymbolAddress((void**)&pos,  g_pos);
    cudaGetSymbolAddress((void**)&ent,  g_ent);
    cudaGetSymbolAddress((void**)&sel,  g_sel);

    const float scale = 1.f / sqrtf((float)DIM);
    const long bnd = (long)SEQ * DIM;          // per-batch stride of x/y slices
    const long smm = (long)SEQ * SEQ;          // one score plane

    // pos_score [N,M]
    pos_softmax<<<SEQ, 256>>>(coords, pe, pos);

    // xu = x @ U^T   : [16384,768] x [768,768]^T
    sgemm_nt<<<dim3(DIM/128, (BATCH*SEQ)/128, 1), 256>>>(
        x, U, xu, BATCH*SEQ, DIM, DIM, 1.f, 0, 0, 0);

    // x1 = (xu*S1^2) @ U ; x2 = (xu*S2^2) @ U
    sgemm_nn_scaled<<<dim3(DIM/128, (BATCH*SEQ)/128, 1), 256>>>(
        xu, U, S1, xs, BATCH*SEQ, DIM, DIM);
    sgemm_nn_scaled<<<dim3(DIM/128, (BATCH*SEQ)/128, 1), 256>>>(
        xu, U, S2, xs + XU_ELEMS, BATCH*SEQ, DIM, DIM);

    // scores[b,h] = scale * xk[b] @ y[b]^T   (batched over b, per head)
    sgemm_nt<<<dim3(SEQ/128, SEQ/128, BATCH), 256>>>(
        xs,            y, attn,       SEQ, SEQ, DIM, scale, bnd, bnd, 2*smm);
    sgemm_nt<<<dim3(SEQ/128, SEQ/128, BATCH), 256>>>(
        xs + XU_ELEMS, y, attn + smm, SEQ, SEQ, DIM, scale, bnd, bnd, 2*smm);

    // softmax + mixture + entropy (in place)
    softmax_mix<<<BATCH*2*SEQ, 256>>>(attn, pos, ent, gating);

    // routing -> sel + heat_map (appended after out)
    route_kernel<<<(BATCH*SEQ + 255)/256, 256>>>(ent, temp, sel, out + XU_ELEMS);

    // out[b] = attn[b, sel] @ y[b]
    sgemm_av_gather<<<dim3(DIM/128, SEQ/128, BATCH), 256>>>(attn, y, sel, out);
}

// round 8
// speedup vs baseline: 1.7334x; 1.7334x over previous
#include <cuda_runtime.h>
#include <cuda_fp16.h>
#include <math.h>
#include <stdint.h>

// ----------------------------------------------------------------------------
// Problem constants (B=16, N=M=1024, DIM=768, 2 heads)
// ----------------------------------------------------------------------------
#define BATCH 16
#define SEQ   1024
#define DIM   768
#define XU_ELEMS (16LL*1024*768)        // 12,582,912

// ----------------------------------------------------------------------------
// Scratch (static device globals — allocation-free)
// ----------------------------------------------------------------------------
__device__ float g_attn[2LL*16*1024*1024];       // scores -> attn [B,2,N,M]
__device__ float g_pos [1024LL*1024];            // pos_score [N,M]
__device__ float g_ent [16*2*1024];              // entropy [B,2,N]
__device__ int   g_sel [16*1024];                // routed head per (b,n)

// fp16 hi/lo split operands (16B-aligned for cp.async / vector access)
__device__ __align__(16) __half g_xh [16LL*1024*768], g_xl [16LL*1024*768];
__device__ __align__(16) __half g_Uh [768*768],       g_Ul [768*768];
__device__ __align__(16) __half g_UTh[768*768],       g_UTl[768*768];
__device__ __align__(16) __half g_yh [16LL*1024*768], g_yl [16LL*1024*768];
__device__ __align__(16) __half g_yTh[16LL*768*1024], g_yTl[16LL*768*1024];
__device__ __align__(16) __half g_s1h[16LL*1024*768], g_s1l[16LL*1024*768];  // xu*S1^2
__device__ __align__(16) __half g_s2h[16LL*1024*768], g_s2l[16LL*1024*768];  // xu*S2^2
__device__ __align__(16) __half g_q1h[16LL*1024*768], g_q1l[16LL*1024*768];  // x1
__device__ __align__(16) __half g_q2h[16LL*1024*768], g_q2l[16LL*1024*768];  // x2
__device__ __align__(16) __half g_ah [16LL*1024*1024], g_al[16LL*1024*1024]; // attn_sel

// ----------------------------------------------------------------------------
// PTX helpers (baseline PTX only — valid on compute_103 non-'a')
// ----------------------------------------------------------------------------
__device__ __forceinline__ uint32_t smem_u32(const void* p) {
    uint32_t a;
    asm("{ .reg .u64 t; cvta.to.shared.u64 t, %1; cvt.u32.u64 %0, t; }" : "=r"(a) : "l"(p));
    return a;
}
#define CP_ASYNC16(dst, src) \
    asm volatile("cp.async.cg.shared.global [%0], [%1], 16;" :: "r"(dst), "l"(src))
#define CP_COMMIT() asm volatile("cp.async.commit_group;")
#define CP_WAIT1()  asm volatile("cp.async.wait_group 1;")

#define LDSM_X4(r0, r1, r2, r3, addr) \
    asm volatile("ldmatrix.sync.aligned.m8n8.x4.shared.b16 {%0,%1,%2,%3}, [%4];" \
                 : "=r"(r0), "=r"(r1), "=r"(r2), "=r"(r3) : "r"(addr))

#define MMA16816(d, a, b) \
    asm volatile("mma.sync.aligned.m16n8k16.row.col.f32.f16.f16.f32 " \
                 "{%0,%1,%2,%3}, {%4,%5,%6,%7}, {%8,%9}, {%0,%1,%2,%3};" \
                 : "+f"((d)[0]), "+f"((d)[1]), "+f"((d)[2]), "+f"((d)[3]) \
                 : "r"((a)[0]), "r"((a)[1]), "r"((a)[2]), "r"((a)[3]), \
                   "r"((b)[0]), "r"((b)[1]))

// ----------------------------------------------------------------------------
// fp16 split helpers
// ----------------------------------------------------------------------------
__device__ __forceinline__ uint32_t hpack2(float a, float b) {
    __half ha = __float2half_rn(a), hb = __float2half_rn(b);
    return ((uint32_t)__half_as_ushort(hb) << 16) | (uint32_t)__half_as_ushort(ha);
}
__device__ __forceinline__ uint32_t hpack_hi2(float a, float b, float& ra, float& rb) {
    __half ha = __float2half_rn(a), hb = __float2half_rn(b);
    ra = a - __half2float(ha);
    rb = b - __half2float(hb);
    return ((uint32_t)__half_as_ushort(hb) << 16) | (uint32_t)__half_as_ushort(ha);
}
__device__ __forceinline__ void store_split(__half* H, __half* L, long off, float a, float b) {
    float ra, rb;
    uint32_t hw = hpack_hi2(a, b, ra, rb);
    *(uint32_t*)(H + off) = hw;
    *(uint32_t*)(L + off) = hpack2(ra, rb);
}

// ----------------------------------------------------------------------------
// Pipelined fp16-split GEMM (mma.sync.m16n8k16, HMMA pipe):
//   C[i,j] = alpha * sum_k (Ahi+Alo)[i,k] * (Bhi+Blo)[j,k]   (passes: hh, lh, hl)
// A: [M,K] k-major, B: [N,K] k-major. M,N mult of 128, K mult of 64.
// Epilogue modes: Cf -> fp32; S1 -> dual scaled fp16-split (C1*,C2*); else fp16-split C1*.
// CTA 128x128, 8 warps (2x4), warp tile 64x32, 3-stage cp.async pipeline, chunk K=64.
// ----------------------------------------------------------------------------
#define GEMM_SMEM (3 * 32768 + 128)

__global__ __launch_bounds__(256, 2)
void gemm_f16_split(const __half* __restrict__ Ahi, const __half* __restrict__ Alo,
                    const __half* __restrict__ Bhi, const __half* __restrict__ Blo,
                    float* __restrict__ Cf,
                    __half* __restrict__ C1h, __half* __restrict__ C1l,
                    __half* __restrict__ C2h, __half* __restrict__ C2l,
                    const float* __restrict__ S1, const float* __restrict__ S2,
                    int M, int N, int K, float alpha,
                    long sA, long sB, long sC)
{
    extern __shared__ char smem_raw[];
    const uint32_t raw_u = smem_u32(smem_raw);
    const uint32_t base  = (raw_u + 127) & ~127u;

    const int tid  = threadIdx.x;
    const int lane = tid & 31;
    const int wid  = tid >> 5;
    const int wm   = wid >> 2;          // 0..1
    const int wn   = wid & 3;           // 0..3

    const int z    = blockIdx.z;
    const int row0 = blockIdx.y * 128;
    const int col0 = blockIdx.x * 128;

    const __half* AP[3] = {Ahi + z * sA, Alo + z * sA, Ahi + z * sA};
    const __half* BP[3] = {Bhi + z * sB, Bhi + z * sB, Blo + z * sB};

    const int kc = K >> 6;              // 64-half chunks per pass
    const int C  = 3 * kc;

    // fill assignment: thread covers row r = tid/2, half-row h = tid%2 (32 halfs = 64B)
    const int fr = tid >> 1;
    const int fh = tid & 1;
    const uint32_t fro = (uint32_t)(fr * 128 + fh * 64);

    auto issue = [&](int c) {
        const int s  = c % 3;
        const int p  = c / kc;
        const int kk = (c - p * kc) << 6;
        const __half* ga = AP[p] + (long)(row0 + fr) * K + kk + fh * 32;
        const __half* gb = BP[p] + (long)(col0 + fr) * K + kk + fh * 32;
        const uint32_t sa = base + s * 32768;
        const uint32_t sb = sa + 16384;
        #pragma unroll
        for (int i = 0; i < 4; i++) {
            uint32_t off = fro + i * 16; off ^= (off >> 3) & 0x70;
            CP_ASYNC16(sa + off, ga + i * 8);
        }
        #pragma unroll
        for (int i = 0; i < 4; i++) {
            uint32_t off = fro + i * 16; off ^= (off >> 3) & 0x70;
            CP_ASYNC16(sb + off, gb + i * 8);
        }
        CP_COMMIT();
    };

    float acc[4][4][4] = {};

    issue(0);
    if (C > 1) issue(1);

    for (int c = 0; c < C; c++) {
        CP_WAIT1();
        __syncthreads();
        if (c + 2 < C) issue(c + 2);

        const uint32_t sa = base + (c % 3) * 32768;
        const uint32_t sb = sa + 16384;

        #pragma unroll
        for (int ks = 0; ks < 4; ks++) {
            uint32_t a[4][4];
            #pragma unroll
            for (int mi = 0; mi < 4; mi++) {
                int r  = wm * 64 + mi * 16 + (lane & 15);
                int cb = (ks * 16 + (lane >> 4) * 8) * 2;
                uint32_t off = (uint32_t)(r * 128 + cb); off ^= (off >> 3) & 0x70;
                LDSM_X4(a[mi][0], a[mi][1], a[mi][2], a[mi][3], sa + off);
            }
            uint32_t b[4][2];
            #pragma unroll
            for (int g = 0; g < 2; g++) {
                int n  = wn * 32 + g * 16 + ((lane >> 4) & 1) * 8 + (lane & 7);
                int cb = (ks * 16 + ((lane >> 3) & 1) * 8) * 2;
                uint32_t off = (uint32_t)(n * 128 + cb); off ^= (off >> 3) & 0x70;
                LDSM_X4(b[2*g][0], b[2*g][1], b[2*g+1][0], b[2*g+1][1], sb + off);
            }
            #pragma unroll
            for (int mi = 0; mi < 4; mi++)
                #pragma unroll
                for (int ni = 0; ni < 4; ni++)
                    MMA16816(acc[mi][ni], a[mi], b[ni]);
        }
        __syncthreads();
    }

    // ------------------------------------------------------------------ epilogue
    const long cb0 = (long)z * sC;
    #pragma unroll
    for (int mi = 0; mi < 4; mi++) {
        #pragma unroll
        for (int ni = 0; ni < 4; ni++) {
            const int r  = row0 + wm * 64 + mi * 16 + (lane >> 2);
            const int cc = col0 + wn * 32 + ni * 8 + (lane & 3) * 2;
            const long o0 = cb0 + (long)r * N + cc;
            const long o1 = o0 + 8L * N;
            const float* av = acc[mi][ni];
            if (Cf) {
                *(float2*)(Cf + o0) = make_float2(av[0] * alpha, av[1] * alpha);
                *(float2*)(Cf + o1) = make_float2(av[2] * alpha, av[3] * alpha);
            } else if (S1) {
                const float s1a = S1[cc], s1b = S1[cc + 1];
                const float s2a = S2[cc], s2b = S2[cc + 1];
                const float q1a = s1a * s1a, q1b = s1b * s1b;
                const float q2a = s2a * s2a, q2b = s2b * s2b;
                store_split(C1h, C1l, o0, av[0] * q1a, av[1] * q1b);
                store_split(C1h, C1l, o1, av[2] * q1a, av[3] * q1b);
                store_split(C2h, C2l, o0, av[0] * q2a, av[1] * q2b);
                store_split(C2h, C2l, o1, av[2] * q2a, av[3] * q2b);
            } else {
                store_split(C1h, C1l, o0, av[0], av[1]);
                store_split(C1h, C1l, o1, av[2], av[3]);
            }
        }
    }
}

// ----------------------------------------------------------------------------
// Conversion kernels (fp32 -> fp16 hi/lo split)
// ----------------------------------------------------------------------------
__global__ void k_split(const float* __restrict__ in, __half* __restrict__ hi,
                        __half* __restrict__ lo, long n4)
{
    long i = (long)blockIdx.x * blockDim.x + threadIdx.x;
    if (i >= n4) return;
    float4 v = ((const float4*)in)[i];
    float r0, r1, r2, r3;
    uint32_t h01 = hpack_hi2(v.x, v.y, r0, r1);
    uint32_t h23 = hpack_hi2(v.z, v.w, r2, r3);
    ((uint2*)hi)[i] = make_uint2(h01, h23);
    ((uint2*)lo)[i] = make_uint2(hpack2(r0, r1), hpack2(r2, r3));
}

// transpose + split: in [R, Cc] fp32 -> out [Cc, R] fp16 hi/lo, batched on z
__global__ void k_split_T(const float* __restrict__ in, __half* __restrict__ hi,
                          __half* __restrict__ lo, int R, int Cc, long sIn, long sOut)
{
    __shared__ float t[32][33];
    const int z  = blockIdx.z;
    const int c0 = blockIdx.x * 32, r0 = blockIdx.y * 32;
    const float* ip = in + (long)z * sIn;
    const int tx = threadIdx.x & 31, ty = threadIdx.x >> 5;
    #pragma unroll
    for (int rr = ty; rr < 32; rr += 8)
        t[rr][tx] = ip[(long)(r0 + rr) * Cc + c0 + tx];
    __syncthreads();
    #pragma unroll
    for (int cc = ty; cc < 32; cc += 8) {
        float v = t[tx][cc];
        __half h = __float2half_rn(v);
        float rl = v - __half2float(h);
        long o = (long)z * sOut + (long)(c0 + cc) * R + r0 + tx;
        hi[o] = h;
        lo[o] = __float2half_rn(rl);
    }
}

// gather selected attn head rows + split: out [B, N, M]
__global__ void k_gather_split(const float* __restrict__ attn, const int* __restrict__ sel,
                               __half* __restrict__ hi, __half* __restrict__ lo)
{
    const int r = blockIdx.x;                   // (b, n)
    const int b = r >> 10, n = r & 1023;
    const int s = sel[r];
    const float4* src = (const float4*)(attn + ((long)(b * 2 + s) * SEQ + n) * SEQ);
    float4 v = src[threadIdx.x];
    float r0, r1, r2, r3;
    uint32_t h01 = hpack_hi2(v.x, v.y, r0, r1);
    uint32_t h23 = hpack_hi2(v.z, v.w, r2, r3);
    long o = (long)r * (SEQ / 4) + threadIdx.x;
    ((uint2*)hi)[o] = make_uint2(h01, h23);
    ((uint2*)lo)[o] = make_uint2(hpack2(r0, r1), hpack2(r2, r3));
}

// ----------------------------------------------------------------------------
// Block reductions (256 threads, 8 warps)
// ----------------------------------------------------------------------------
__device__ __forceinline__ float block_sum(float v, float* red) {
    #pragma unroll
    for (int o = 16; o; o >>= 1) v += __shfl_xor_sync(0xffffffffu, v, o);
    __syncthreads();
    if ((threadIdx.x & 31) == 0) red[threadIdx.x >> 5] = v;
    __syncthreads();
    float r = red[0];
    #pragma unroll
    for (int w = 1; w < 8; w++) r += red[w];
    return r;
}
__device__ __forceinline__ float block_max(float v, float* red) {
    #pragma unroll
    for (int o = 16; o; o >>= 1) v = fmaxf(v, __shfl_xor_sync(0xffffffffu, v, o));
    __syncthreads();
    if ((threadIdx.x & 31) == 0) red[threadIdx.x >> 5] = v;
    __syncthreads();
    float r = red[0];
    #pragma unroll
    for (int w = 1; w < 8; w++) r = fmaxf(r, red[w]);
    return r;
}

// ----------------------------------------------------------------------------
// pos_score softmax
// ----------------------------------------------------------------------------
__global__ void pos_softmax(const float* __restrict__ coords, const float* __restrict__ pe,
                            float* __restrict__ pos)
{
    const int n   = blockIdx.x;
    const int tid = threadIdx.x;
    __shared__ float red[8];
    __shared__ float w[6];
    if (tid < 6) w[tid] = pe[n * 6 + tid];
    __syncthreads();

    float p[4];
    #pragma unroll
    for (int i = 0; i < 4; i++) {
        const float* c = coords + ((long)n * SEQ + tid * 4 + i) * 6;
        p[i] = w[0]*c[0] + w[1]*c[1] + w[2]*c[2] + w[3]*c[3] + w[4]*c[4] + w[5]*c[5];
    }
    float mx = fmaxf(fmaxf(p[0], p[1]), fmaxf(p[2], p[3]));
    mx = block_max(mx, red);
    float e[4], sum = 0.f;
    #pragma unroll
    for (int i = 0; i < 4; i++) { e[i] = expf(p[i] - mx); sum += e[i]; }
    sum = block_sum(sum, red);
    float inv = 1.f / sum;
    *(float4*)(pos + (long)n * SEQ + tid * 4) = make_float4(e[0]*inv, e[1]*inv, e[2]*inv, e[3]*inv);
}

// ----------------------------------------------------------------------------
// Fused softmax + gating mixture + entropy (in place on g_attn)
// ----------------------------------------------------------------------------
__global__ void softmax_mix(float* __restrict__ attn, const float* __restrict__ pos,
                            float* __restrict__ ent, const float* __restrict__ gating)
{
    const long r  = blockIdx.x;
    const int  n  = (int)(r & (SEQ - 1));
    const int tid = threadIdx.x;
    __shared__ float red[8];

    float* row = attn + r * SEQ;
    const float* q = pos + (long)n * SEQ;

    float4 v = *(const float4*)(row + tid * 4);
    float mx = fmaxf(fmaxf(v.x, v.y), fmaxf(v.z, v.w));
    mx = block_max(mx, red);

    float4 e;
    e.x = expf(v.x - mx); e.y = expf(v.y - mx);
    e.z = expf(v.z - mx); e.w = expf(v.w - mx);
    float sum = e.x + e.y + e.z + e.w;
    sum = block_sum(sum, red);

    float g   = 1.f / (1.f + expf(-gating[0]));
    float omg = (1.f - g) / sum;
    float4 qv = *(const float4*)(q + tid * 4);
    float4 a;
    a.x = omg*e.x + g*qv.x; a.y = omg*e.y + g*qv.y;
    a.z = omg*e.z + g*qv.z; a.w = omg*e.w + g*qv.w;

    float ep = -(a.x * logf(a.x + 1e-8f) + a.y * logf(a.y + 1e-8f)
               + a.z * logf(a.z + 1e-8f) + a.w * logf(a.w + 1e-8f));
    ep = block_sum(ep, red);

    *(float4*)(row + tid * 4) = a;
    if (tid == 0) ent[r] = ep;
}

// ----------------------------------------------------------------------------
// Entropy routing
// ----------------------------------------------------------------------------
__global__ void route_kernel(const float* __restrict__ ent, const float* __restrict__ temp,
                             int* __restrict__ sel, float* __restrict__ heat)
{
    const int i = blockIdx.x * blockDim.x + threadIdx.x;
    if (i >= BATCH * SEQ) return;
    const int b = i >> 10, n = i & 1023;
    const float t  = temp[0];
    const float e0 = ent[b * 2048 + n];
    const float e1 = ent[b * 2048 + 1024 + n];
    const float h0 = 2.f - 2.f / (1.f + expf(-t * e0));
    const float h1 = 2.f - 2.f / (1.f + expf(-t * e1));
    const int s = (h0 >= h1) ? 0 : 1;
    sel[i]  = s;
    heat[i] = s ? h1 : h0;
}

// ----------------------------------------------------------------------------
// kernel_launch
// Inputs: 0:x 1:y 2:coords 3:U 4:S1 5:S2 6:gating 7:temp 8:pos_emb
// Output: out [B,N,DIM] (12,582,912 f32) then heat_map [B,N,1] (16,384 f32)
// ----------------------------------------------------------------------------
extern "C" void kernel_launch(void* const* d_in, const int* in_sizes, int n_in,
                              void* d_out, int out_size)
{
    const float* x      = (const float*)d_in[0];
    const float* y      = (const float*)d_in[1];
    const float* coords = (const float*)d_in[2];
    const float* U      = (const float*)d_in[3];
    const float* S1     = (const float*)d_in[4];
    const float* S2     = (const float*)d_in[5];
    const float* gating = (const float*)d_in[6];
    const float* temp   = (const float*)d_in[7];
    const float* pe     = (const float*)d_in[8];
    float* out = (float*)d_out;

    float *attn, *pos, *ent; int* sel;
    __half *xh, *xl, *Uh, *Ul, *UTh, *UTl, *yh, *yl, *yTh, *yTl;
    __half *s1h, *s1l, *s2h, *s2l, *q1h, *q1l, *q2h, *q2l, *ah, *al;
    cudaGetSymbolAddress((void**)&attn, g_attn);
    cudaGetSymbolAddress((void**)&pos,  g_pos);
    cudaGetSymbolAddress((void**)&ent,  g_ent);
    cudaGetSymbolAddress((void**)&sel,  g_sel);
    cudaGetSymbolAddress((void**)&xh,  g_xh);   cudaGetSymbolAddress((void**)&xl,  g_xl);
    cudaGetSymbolAddress((void**)&Uh,  g_Uh);   cudaGetSymbolAddress((void**)&Ul,  g_Ul);
    cudaGetSymbolAddress((void**)&UTh, g_UTh);  cudaGetSymbolAddress((void**)&UTl, g_UTl);
    cudaGetSymbolAddress((void**)&yh,  g_yh);   cudaGetSymbolAddress((void**)&yl,  g_yl);
    cudaGetSymbolAddress((void**)&yTh, g_yTh);  cudaGetSymbolAddress((void**)&yTl, g_yTl);
    cudaGetSymbolAddress((void**)&s1h, g_s1h);  cudaGetSymbolAddress((void**)&s1l, g_s1l);
    cudaGetSymbolAddress((void**)&s2h, g_s2h);  cudaGetSymbolAddress((void**)&s2l, g_s2l);
    cudaGetSymbolAddress((void**)&q1h, g_q1h);  cudaGetSymbolAddress((void**)&q1l, g_q1l);
    cudaGetSymbolAddress((void**)&q2h, g_q2h);  cudaGetSymbolAddress((void**)&q2l, g_q2l);
    cudaGetSymbolAddress((void**)&ah,  g_ah);   cudaGetSymbolAddress((void**)&al,  g_al);

    cudaFuncSetAttribute(gemm_f16_split,
                         cudaFuncAttributeMaxDynamicSharedMemorySize, GEMM_SMEM);

    const float scale = 1.f / sqrtf((float)DIM);
    const long bnd = (long)SEQ * DIM;   // per-batch stride of x/y slices
    const long smm = (long)SEQ * SEQ;   // one score plane

    // input splits
    k_split<<<(int)((XU_ELEMS/4 + 255)/256), 256>>>(x, xh, xl, XU_ELEMS/4);
    k_split<<<(768*768/4 + 255)/256, 256>>>(U, Uh, Ul, 768*768/4);
    k_split_T<<<dim3(768/32, 768/32, 1), 256>>>(U, UTh, UTl, 768, 768, 0, 0);
    k_split<<<(int)((XU_ELEMS/4 + 255)/256), 256>>>(y, yh, yl, XU_ELEMS/4);
    k_split_T<<<dim3(768/32, 1024/32, BATCH), 256>>>(y, yTh, yTl, 1024, 768,
                                                     bnd, (long)768*1024);
    pos_softmax<<<SEQ, 256>>>(coords, pe, pos);

    // G1: xu = x @ U^T, fused dual-scale epilogue -> s1 = xu*S1^2, s2 = xu*S2^2 (fp16 split)
    gemm_f16_split<<<dim3(DIM/128, (BATCH*SEQ)/128, 1), 256, GEMM_SMEM>>>(
        xh, xl, Uh, Ul, nullptr, s1h, s1l, s2h, s2l, S1, S2,
        BATCH*SEQ, DIM, DIM, 1.f, 0, 0, 0);

    // G2: x1 = s1 @ U,  x2 = s2 @ U   (B = U^T k-major) -> fp16 split out
    gemm_f16_split<<<dim3(DIM/128, (BATCH*SEQ)/128, 1), 256, GEMM_SMEM>>>(
        s1h, s1l, UTh, UTl, nullptr, q1h, q1l, nullptr, nullptr, nullptr, nullptr,
        BATCH*SEQ, DIM, DIM, 1.f, 0, 0, 0);
    gemm_f16_split<<<dim3(DIM/128, (BATCH*SEQ)/128, 1), 256, GEMM_SMEM>>>(
        s2h, s2l, UTh, UTl, nullptr, q2h, q2l, nullptr, nullptr, nullptr, nullptr,
        BATCH*SEQ, DIM, DIM, 1.f, 0, 0, 0);

    // G3: scores[b,h] = scale * xk[b] @ y[b]^T  (batched over b per head)
    gemm_f16_split<<<dim3(SEQ/128, SEQ/128, BATCH), 256, GEMM_SMEM>>>(
        q1h, q1l, yh, yl, attn,       nullptr, nullptr, nullptr, nullptr, nullptr, nullptr,
        SEQ, SEQ, DIM, scale, bnd, bnd, 2*smm);
    gemm_f16_split<<<dim3(SEQ/128, SEQ/128, BATCH), 256, GEMM_SMEM>>>(
        q2h, q2l, yh, yl, attn + smm, nullptr, nullptr, nullptr, nullptr, nullptr, nullptr,
        SEQ, SEQ, DIM, scale, bnd, bnd, 2*smm);

    // softmax + mixture + entropy (in place)
    softmax_mix<<<BATCH*2*SEQ, 256>>>(attn, pos, ent, gating);

    // routing -> sel + heat_map (appended after out)
    route_kernel<<<(BATCH*SEQ + 255)/256, 256>>>(ent, temp, sel, out + XU_ELEMS);

    // gather selected head + split
    k_gather_split<<<BATCH*SEQ, 256>>>(attn, sel, ah, al);

    // G4: out[b] = attn_sel[b] @ y[b]   (B = y[b]^T k-major over m)
    gemm_f16_split<<<dim3(DIM/128, SEQ/128, BATCH), 256, GEMM_SMEM>>>(
        ah, al, yTh, yTl, out, nullptr, nullptr, nullptr, nullptr, nullptr, nullptr,
        SEQ, DIM, SEQ, 1.f, smm, (long)768*1024, bnd);
}

// round 9
// speedup vs baseline: 2.0509x; 1.1832x over previous
#include <cuda_runtime.h>
#include <cuda_fp16.h>
#include <math.h>
#include <stdint.h>

// ----------------------------------------------------------------------------
// Problem constants (B=16, N=M=1024, DIM=768, 2 heads)
// ----------------------------------------------------------------------------
#define BATCH 16
#define SEQ   1024
#define DIM   768
#define XU_ELEMS (16LL*1024*768)        // 12,582,912

// ----------------------------------------------------------------------------
// Scratch (static device globals — allocation-free)
// ----------------------------------------------------------------------------
__device__ float g_attn[2LL*16*1024*1024];       // raw scores [B,2,N,M]
__device__ float g_pos [1024LL*1024];            // pos_score [N,M]

// fp16 hi/lo split operands (16B-aligned for cp.async / vector access)
__device__ __align__(16) __half g_xh [16LL*1024*768], g_xl [16LL*1024*768];
__device__ __align__(16) __half g_Uh [768*768],       g_Ul [768*768];
__device__ __align__(16) __half g_UTh[768*768],       g_UTl[768*768];
__device__ __align__(16) __half g_yh [16LL*1024*768], g_yl [16LL*1024*768];
__device__ __align__(16) __half g_yTh[16LL*768*1024], g_yTl[16LL*768*1024];
__device__ __align__(16) __half g_s1h[16LL*1024*768], g_s1l[16LL*1024*768];  // xu*S1^2
__device__ __align__(16) __half g_s2h[16LL*1024*768], g_s2l[16LL*1024*768];  // xu*S2^2
__device__ __align__(16) __half g_q1h[16LL*1024*768], g_q1l[16LL*1024*768];  // x1
__device__ __align__(16) __half g_q2h[16LL*1024*768], g_q2l[16LL*1024*768];  // x2
__device__ __align__(16) __half g_ah [16LL*1024*1024], g_al[16LL*1024*1024]; // attn_sel

// ----------------------------------------------------------------------------
// PTX helpers (baseline PTX only — valid on compute_103 non-'a')
// ----------------------------------------------------------------------------
__device__ __forceinline__ uint32_t smem_u32(const void* p) {
    uint32_t a;
    asm("{ .reg .u64 t; cvta.to.shared.u64 t, %1; cvt.u32.u64 %0, t; }" : "=r"(a) : "l"(p));
    return a;
}
#define CP_ASYNC16(dst, src) \
    asm volatile("cp.async.cg.shared.global [%0], [%1], 16;" :: "r"(dst), "l"(src))
#define CP_COMMIT() asm volatile("cp.async.commit_group;")
#define CP_WAIT1()  asm volatile("cp.async.wait_group 1;")

#define LDSM_X4(r0, r1, r2, r3, addr) \
    asm volatile("ldmatrix.sync.aligned.m8n8.x4.shared.b16 {%0,%1,%2,%3}, [%4];" \
                 : "=r"(r0), "=r"(r1), "=r"(r2), "=r"(r3) : "r"(addr))

#define MMA16816(d, a, b) \
    asm volatile("mma.sync.aligned.m16n8k16.row.col.f32.f16.f16.f32 " \
                 "{%0,%1,%2,%3}, {%4,%5,%6,%7}, {%8,%9}, {%0,%1,%2,%3};" \
                 : "+f"((d)[0]), "+f"((d)[1]), "+f"((d)[2]), "+f"((d)[3]) \
                 : "r"((a)[0]), "r"((a)[1]), "r"((a)[2]), "r"((a)[3]), \
                   "r"((b)[0]), "r"((b)[1]))

// ----------------------------------------------------------------------------
// fp16 split helpers
// ----------------------------------------------------------------------------
__device__ __forceinline__ uint32_t hpack2(float a, float b) {
    __half ha = __float2half_rn(a), hb = __float2half_rn(b);
    return ((uint32_t)__half_as_ushort(hb) << 16) | (uint32_t)__half_as_ushort(ha);
}
__device__ __forceinline__ uint32_t hpack_hi2(float a, float b, float& ra, float& rb) {
    __half ha = __float2half_rn(a), hb = __float2half_rn(b);
    ra = a - __half2float(ha);
    rb = b - __half2float(hb);
    return ((uint32_t)__half_as_ushort(hb) << 16) | (uint32_t)__half_as_ushort(ha);
}
__device__ __forceinline__ void store_split(__half* H, __half* L, long off, float a, float b) {
    float ra, rb;
    uint32_t hw = hpack_hi2(a, b, ra, rb);
    *(uint32_t*)(H + off) = hw;
    *(uint32_t*)(L + off) = hpack2(ra, rb);
}

// ----------------------------------------------------------------------------
// Pipelined fp16-split GEMM (mma.sync.m16n8k16, HMMA pipe):
//   C[i,j] = alpha * sum_k (Ahi+Alo)[i,k] * (Bhi+Blo)[j,k]
// npass = 3: hh + lh + hl ; npass = 2: hh + lh (drops Ahi@Blo, ~2^-12 rel).
// A: [M,K] k-major, B: [N,K] k-major. M,N mult of 128, K mult of 64.
// Epilogue modes: Cf -> fp32; S1 -> dual scaled fp16-split (C1*,C2*); else fp16-split C1*.
// CTA 128x128, 8 warps (2x4), warp tile 64x32, 3-stage cp.async pipeline, chunk K=64.
// ----------------------------------------------------------------------------
#define GEMM_SMEM (3 * 32768 + 128)

__global__ __launch_bounds__(256, 2)
void gemm_f16_split(const __half* __restrict__ Ahi, const __half* __restrict__ Alo,
                    const __half* __restrict__ Bhi, const __half* __restrict__ Blo,
                    float* __restrict__ Cf,
                    __half* __restrict__ C1h, __half* __restrict__ C1l,
                    __half* __restrict__ C2h, __half* __restrict__ C2l,
                    const float* __restrict__ S1, const float* __restrict__ S2,
                    int M, int N, int K, float alpha,
                    long sA, long sB, long sC, int npass)
{
    extern __shared__ char smem_raw[];
    const uint32_t raw_u = smem_u32(smem_raw);
    const uint32_t base  = (raw_u + 127) & ~127u;

    const int tid  = threadIdx.x;
    const int lane = tid & 31;
    const int wid  = tid >> 5;
    const int wm   = wid >> 2;          // 0..1
    const int wn   = wid & 3;           // 0..3

    const int z    = blockIdx.z;
    const int row0 = blockIdx.y * 128;
    const int col0 = blockIdx.x * 128;

    const __half* AP[3] = {Ahi + z * sA, Alo + z * sA, Ahi + z * sA};
    const __half* BP[3] = {Bhi + z * sB, Bhi + z * sB, Blo + z * sB};

    const int kc = K >> 6;              // 64-half chunks per pass
    const int C  = npass * kc;

    // fill assignment: thread covers row r = tid/2, half-row h = tid%2 (32 halfs = 64B)
    const int fr = tid >> 1;
    const int fh = tid & 1;
    const uint32_t fro = (uint32_t)(fr * 128 + fh * 64);

    auto issue = [&](int c) {
        const int s  = c % 3;
        const int p  = c / kc;
        const int kk = (c - p * kc) << 6;
        const __half* ga = AP[p] + (long)(row0 + fr) * K + kk + fh * 32;
        const __half* gb = BP[p] + (long)(col0 + fr) * K + kk + fh * 32;
        const uint32_t sa = base + s * 32768;
        const uint32_t sb = sa + 16384;
        #pragma unroll
        for (int i = 0; i < 4; i++) {
            uint32_t off = fro + i * 16; off ^= (off >> 3) & 0x70;
            CP_ASYNC16(sa + off, ga + i * 8);
        }
        #pragma unroll
        for (int i = 0; i < 4; i++) {
            uint32_t off = fro + i * 16; off ^= (off >> 3) & 0x70;
            CP_ASYNC16(sb + off, gb + i * 8);
        }
        CP_COMMIT();
    };

    float acc[4][4][4] = {};

    issue(0);
    if (C > 1) issue(1);

    for (int c = 0; c < C; c++) {
        CP_WAIT1();
        __syncthreads();
        if (c + 2 < C) issue(c + 2);

        const uint32_t sa = base + (c % 3) * 32768;
        const uint32_t sb = sa + 16384;

        #pragma unroll
        for (int ks = 0; ks < 4; ks++) {
            uint32_t a[4][4];
            #pragma unroll
            for (int mi = 0; mi < 4; mi++) {
                int r  = wm * 64 + mi * 16 + (lane & 15);
                int cb = (ks * 16 + (lane >> 4) * 8) * 2;
                uint32_t off = (uint32_t)(r * 128 + cb); off ^= (off >> 3) & 0x70;
                LDSM_X4(a[mi][0], a[mi][1], a[mi][2], a[mi][3], sa + off);
            }
            uint32_t b[4][2];
            #pragma unroll
            for (int g = 0; g < 2; g++) {
                int n  = wn * 32 + g * 16 + ((lane >> 4) & 1) * 8 + (lane & 7);
                int cb = (ks * 16 + ((lane >> 3) & 1) * 8) * 2;
                uint32_t off = (uint32_t)(n * 128 + cb); off ^= (off >> 3) & 0x70;
                LDSM_X4(b[2*g][0], b[2*g][1], b[2*g+1][0], b[2*g+1][1], sb + off);
            }
            #pragma unroll
            for (int mi = 0; mi < 4; mi++)
                #pragma unroll
                for (int ni = 0; ni < 4; ni++)
                    MMA16816(acc[mi][ni], a[mi], b[ni]);
        }
        __syncthreads();
    }

    // ------------------------------------------------------------------ epilogue
    const long cb0 = (long)z * sC;
    #pragma unroll
    for (int mi = 0; mi < 4; mi++) {
        #pragma unroll
        for (int ni = 0; ni < 4; ni++) {
            const int r  = row0 + wm * 64 + mi * 16 + (lane >> 2);
            const int cc = col0 + wn * 32 + ni * 8 + (lane & 3) * 2;
            const long o0 = cb0 + (long)r * N + cc;
            const long o1 = o0 + 8L * N;
            const float* av = acc[mi][ni];
            if (Cf) {
                *(float2*)(Cf + o0) = make_float2(av[0] * alpha, av[1] * alpha);
                *(float2*)(Cf + o1) = make_float2(av[2] * alpha, av[3] * alpha);
            } else if (S1) {
                const float s1a = S1[cc], s1b = S1[cc + 1];
                const float s2a = S2[cc], s2b = S2[cc + 1];
                const float q1a = s1a * s1a, q1b = s1b * s1b;
                const float q2a = s2a * s2a, q2b = s2b * s2b;
                store_split(C1h, C1l, o0, av[0] * q1a, av[1] * q1b);
                store_split(C1h, C1l, o1, av[2] * q1a, av[3] * q1b);
                store_split(C2h, C2l, o0, av[0] * q2a, av[1] * q2b);
                store_split(C2h, C2l, o1, av[2] * q2a, av[3] * q2b);
            } else {
                store_split(C1h, C1l, o0, av[0], av[1]);
                store_split(C1h, C1l, o1, av[2], av[3]);
            }
        }
    }
}

// ----------------------------------------------------------------------------
// Conversion kernels (fp32 -> fp16 hi/lo split)
// ----------------------------------------------------------------------------
__global__ void k_split(const float* __restrict__ in, __half* __restrict__ hi,
                        __half* __restrict__ lo, long n4)
{
    long i = (long)blockIdx.x * blockDim.x + threadIdx.x;
    if (i >= n4) return;
    float4 v = ((const float4*)in)[i];
    float r0, r1, r2, r3;
    uint32_t h01 = hpack_hi2(v.x, v.y, r0, r1);
    uint32_t h23 = hpack_hi2(v.z, v.w, r2, r3);
    ((uint2*)hi)[i] = make_uint2(h01, h23);
    ((uint2*)lo)[i] = make_uint2(hpack2(r0, r1), hpack2(r2, r3));
}

// transpose + split: in [R, Cc] fp32 -> out [Cc, R] fp16 hi/lo, batched on z
__global__ void k_split_T(const float* __restrict__ in, __half* __restrict__ hi,
                          __half* __restrict__ lo, int R, int Cc, long sIn, long sOut)
{
    __shared__ float t[32][33];
    const int z  = blockIdx.z;
    const int c0 = blockIdx.x * 32, r0 = blockIdx.y * 32;
    const float* ip = in + (long)z * sIn;
    const int tx = threadIdx.x & 31, ty = threadIdx.x >> 5;
    #pragma unroll
    for (int rr = ty; rr < 32; rr += 8)
        t[rr][tx] = ip[(long)(r0 + rr) * Cc + c0 + tx];
    __syncthreads();
    #pragma unroll
    for (int cc = ty; cc < 32; cc += 8) {
        float v = t[tx][cc];
        __half h = __float2half_rn(v);
        float rl = v - __half2float(h);
        long o = (long)z * sOut + (long)(c0 + cc) * R + r0 + tx;
        hi[o] = h;
        lo[o] = __float2half_rn(rl);
    }
}

// ----------------------------------------------------------------------------
// Block reductions (256 threads, 8 warps)
// ----------------------------------------------------------------------------
__device__ __forceinline__ float block_sum(float v, float* red) {
    #pragma unroll
    for (int o = 16; o; o >>= 1) v += __shfl_xor_sync(0xffffffffu, v, o);
    __syncthreads();
    if ((threadIdx.x & 31) == 0) red[threadIdx.x >> 5] = v;
    __syncthreads();
    float r = red[0];
    #pragma unroll
    for (int w = 1; w < 8; w++) r += red[w];
    return r;
}
__device__ __forceinline__ float block_max(float v, float* red) {
    #pragma unroll
    for (int o = 16; o; o >>= 1) v = fmaxf(v, __shfl_xor_sync(0xffffffffu, v, o));
    __syncthreads();
    if ((threadIdx.x & 31) == 0) red[threadIdx.x >> 5] = v;
    __syncthreads();
    float r = red[0];
    #pragma unroll
    for (int w = 1; w < 8; w++) r = fmaxf(r, red[w]);
    return r;
}

// ----------------------------------------------------------------------------
// pos_score softmax
// ----------------------------------------------------------------------------
__global__ void pos_softmax(const float* __restrict__ coords, const float* __restrict__ pe,
                            float* __restrict__ pos)
{
    const int n   = blockIdx.x;
    const int tid = threadIdx.x;
    __shared__ float red[8];
    __shared__ float w[6];
    if (tid < 6) w[tid] = pe[n * 6 + tid];
    __syncthreads();

    float p[4];
    #pragma unroll
    for (int i = 0; i < 4; i++) {
        const float* c = coords + ((long)n * SEQ + tid * 4 + i) * 6;
        p[i] = w[0]*c[0] + w[1]*c[1] + w[2]*c[2] + w[3]*c[3] + w[4]*c[4] + w[5]*c[5];
    }
    float mx = fmaxf(fmaxf(p[0], p[1]), fmaxf(p[2], p[3]));
    mx = block_max(mx, red);
    float e[4], sum = 0.f;
    #pragma unroll
    for (int i = 0; i < 4; i++) { e[i] = expf(p[i] - mx); sum += e[i]; }
    sum = block_sum(sum, red);
    float inv = 1.f / sum;
    *(float4*)(pos + (long)n * SEQ + tid * 4) = make_float4(e[0]*inv, e[1]*inv, e[2]*inv, e[3]*inv);
}

// ----------------------------------------------------------------------------
// FUSED: softmax + gating mixture + entropy + routing + head-select + fp16 split.
// One block per (b,n): processes BOTH heads' score rows, routes, and writes
// only the selected attn row (fp16 hi/lo) + heat_map. No fp32 attn writeback.
// ----------------------------------------------------------------------------
__global__ void softmax_route_fused(const float* __restrict__ scores,
                                    const float* __restrict__ pos,
                                    const float* __restrict__ gating,
                                    const float* __restrict__ temp,
                                    __half* __restrict__ ah, __half* __restrict__ al,
                                    float* __restrict__ heat)
{
    const int r   = blockIdx.x;                 // (b, n)
    const int b   = r >> 10, n = r & 1023;
    const int tid = threadIdx.x;
    __shared__ float red[8];

    const float* row0 = scores + ((long)(b * 2 + 0) * SEQ + n) * SEQ;
    const float* row1 = scores + ((long)(b * 2 + 1) * SEQ + n) * SEQ;
    const float* q    = pos + (long)n * SEQ;

    float4 v0 = *(const float4*)(row0 + tid * 4);
    float4 v1 = *(const float4*)(row1 + tid * 4);
    float4 qv = *(const float4*)(q + tid * 4);

    float mx0 = fmaxf(fmaxf(v0.x, v0.y), fmaxf(v0.z, v0.w));
    float mx1 = fmaxf(fmaxf(v1.x, v1.y), fmaxf(v1.z, v1.w));
    mx0 = block_max(mx0, red);
    mx1 = block_max(mx1, red);

    float4 e0, e1;
    e0.x = expf(v0.x - mx0); e0.y = expf(v0.y - mx0);
    e0.z = expf(v0.z - mx0); e0.w = expf(v0.w - mx0);
    e1.x = expf(v1.x - mx1); e1.y = expf(v1.y - mx1);
    e1.z = expf(v1.z - mx1); e1.w = expf(v1.w - mx1);
    float sum0 = block_sum(e0.x + e0.y + e0.z + e0.w, red);
    float sum1 = block_sum(e1.x + e1.y + e1.z + e1.w, red);

    const float g    = 1.f / (1.f + expf(-gating[0]));
    const float omg0 = (1.f - g) / sum0;
    const float omg1 = (1.f - g) / sum1;

    float4 a0, a1;
    a0.x = omg0*e0.x + g*qv.x; a0.y = omg0*e0.y + g*qv.y;
    a0.z = omg0*e0.z + g*qv.z; a0.w = omg0*e0.w + g*qv.w;
    a1.x = omg1*e1.x + g*qv.x; a1.y = omg1*e1.y + g*qv.y;
    a1.z = omg1*e1.z + g*qv.z; a1.w = omg1*e1.w + g*qv.w;

    float ep0 = -(a0.x * logf(a0.x + 1e-8f) + a0.y * logf(a0.y + 1e-8f)
                + a0.z * logf(a0.z + 1e-8f) + a0.w * logf(a0.w + 1e-8f));
    float ep1 = -(a1.x * logf(a1.x + 1e-8f) + a1.y * logf(a1.y + 1e-8f)
                + a1.z * logf(a1.z + 1e-8f) + a1.w * logf(a1.w + 1e-8f));
    ep0 = block_sum(ep0, red);
    ep1 = block_sum(ep1, red);

    const float t  = temp[0];
    const float h0 = 2.f - 2.f / (1.f + expf(-t * ep0));
    const float h1 = 2.f - 2.f / (1.f + expf(-t * ep1));
    const int   s  = (h0 >= h1) ? 0 : 1;

    if (tid == 0) heat[r] = s ? h1 : h0;

    const float4 a = s ? a1 : a0;
    float r0a, r1a, r2a, r3a;
    uint32_t h01 = hpack_hi2(a.x, a.y, r0a, r1a);
    uint32_t h23 = hpack_hi2(a.z, a.w, r2a, r3a);
    const long o = (long)r * (SEQ / 4) + tid;
    ((uint2*)ah)[o] = make_uint2(h01, h23);
    ((uint2*)al)[o] = make_uint2(hpack2(r0a, r1a), hpack2(r2a, r3a));
}

// ----------------------------------------------------------------------------
// kernel_launch
// Inputs: 0:x 1:y 2:coords 3:U 4:S1 5:S2 6:gating 7:temp 8:pos_emb
// Output: out [B,N,DIM] (12,582,912 f32) then heat_map [B,N,1] (16,384 f32)
// ----------------------------------------------------------------------------
extern "C" void kernel_launch(void* const* d_in, const int* in_sizes, int n_in,
                              void* d_out, int out_size)
{
    const float* x      = (const float*)d_in[0];
    const float* y      = (const float*)d_in[1];
    const float* coords = (const float*)d_in[2];
    const float* U      = (const float*)d_in[3];
    const float* S1     = (const float*)d_in[4];
    const float* S2     = (const float*)d_in[5];
    const float* gating = (const float*)d_in[6];
    const float* temp   = (const float*)d_in[7];
    const float* pe     = (const float*)d_in[8];
    float* out = (float*)d_out;

    float *attn, *pos;
    __half *xh, *xl, *Uh, *Ul, *UTh, *UTl, *yh, *yl, *yTh, *yTl;
    __half *s1h, *s1l, *s2h, *s2l, *q1h, *q1l, *q2h, *q2l, *ah, *al;
    cudaGetSymbolAddress((void**)&attn, g_attn);
    cudaGetSymbolAddress((void**)&pos,  g_pos);
    cudaGetSymbolAddress((void**)&xh,  g_xh);   cudaGetSymbolAddress((void**)&xl,  g_xl);
    cudaGetSymbolAddress((void**)&Uh,  g_Uh);   cudaGetSymbolAddress((void**)&Ul,  g_Ul);
    cudaGetSymbolAddress((void**)&UTh, g_UTh);  cudaGetSymbolAddress((void**)&UTl, g_UTl);
    cudaGetSymbolAddress((void**)&yh,  g_yh);   cudaGetSymbolAddress((void**)&yl,  g_yl);
    cudaGetSymbolAddress((void**)&yTh, g_yTh);  cudaGetSymbolAddress((void**)&yTl, g_yTl);
    cudaGetSymbolAddress((void**)&s1h, g_s1h);  cudaGetSymbolAddress((void**)&s1l, g_s1l);
    cudaGetSymbolAddress((void**)&s2h, g_s2h);  cudaGetSymbolAddress((void**)&s2l, g_s2l);
    cudaGetSymbolAddress((void**)&q1h, g_q1h);  cudaGetSymbolAddress((void**)&q1l, g_q1l);
    cudaGetSymbolAddress((void**)&q2h, g_q2h);  cudaGetSymbolAddress((void**)&q2l, g_q2l);
    cudaGetSymbolAddress((void**)&ah,  g_ah);   cudaGetSymbolAddress((void**)&al,  g_al);

    cudaFuncSetAttribute(gemm_f16_split,
                         cudaFuncAttributeMaxDynamicSharedMemorySize, GEMM_SMEM);

    const float scale = 1.f / sqrtf((float)DIM);
    const long bnd = (long)SEQ * DIM;   // per-batch stride of x/y slices
    const long smm = (long)SEQ * SEQ;   // one score plane

    // input splits
    k_split<<<(int)((XU_ELEMS/4 + 255)/256), 256>>>(x, xh, xl, XU_ELEMS/4);
    k_split<<<(768*768/4 + 255)/256, 256>>>(U, Uh, Ul, 768*768/4);
    k_split_T<<<dim3(768/32, 768/32, 1), 256>>>(U, UTh, UTl, 768, 768, 0, 0);
    k_split<<<(int)((XU_ELEMS/4 + 255)/256), 256>>>(y, yh, yl, XU_ELEMS/4);
    k_split_T<<<dim3(768/32, 1024/32, BATCH), 256>>>(y, yTh, yTl, 1024, 768,
                                                     bnd, (long)768*1024);
    pos_softmax<<<SEQ, 256>>>(coords, pe, pos);

    // G1: xu = x @ U^T, fused dual-scale epilogue -> s1 = xu*S1^2, s2 = xu*S2^2 (3-pass)
    gemm_f16_split<<<dim3(DIM/128, (BATCH*SEQ)/128, 1), 256, GEMM_SMEM>>>(
        xh, xl, Uh, Ul, nullptr, s1h, s1l, s2h, s2l, S1, S2,
        BATCH*SEQ, DIM, DIM, 1.f, 0, 0, 0, 3);

    // G2: x1 = s1 @ U,  x2 = s2 @ U   (B = U^T k-major) -> fp16 split out (3-pass)
    gemm_f16_split<<<dim3(DIM/128, (BATCH*SEQ)/128, 1), 256, GEMM_SMEM>>>(
        s1h, s1l, UTh, UTl, nullptr, q1h, q1l, nullptr, nullptr, nullptr, nullptr,
        BATCH*SEQ, DIM, DIM, 1.f, 0, 0, 0, 3);
    gemm_f16_split<<<dim3(DIM/128, (BATCH*SEQ)/128, 1), 256, GEMM_SMEM>>>(
        s2h, s2l, UTh, UTl, nullptr, q2h, q2l, nullptr, nullptr, nullptr, nullptr,
        BATCH*SEQ, DIM, DIM, 1.f, 0, 0, 0, 3);

    // G3: scores[b,h] = scale * xk[b] @ y[b]^T  (batched over b per head, 2-pass)
    gemm_f16_split<<<dim3(SEQ/128, SEQ/128, BATCH), 256, GEMM_SMEM>>>(
        q1h, q1l, yh, yl, attn,       nullptr, nullptr, nullptr, nullptr, nullptr, nullptr,
        SEQ, SEQ, DIM, scale, bnd, bnd, 2*smm, 2);
    gemm_f16_split<<<dim3(SEQ/128, SEQ/128, BATCH), 256, GEMM_SMEM>>>(
        q2h, q2l, yh, yl, attn + smm, nullptr, nullptr, nullptr, nullptr, nullptr, nullptr,
        SEQ, SEQ, DIM, scale, bnd, bnd, 2*smm, 2);

    // fused softmax + mixture + entropy + route + gather-split + heat
    softmax_route_fused<<<BATCH*SEQ, 256>>>(attn, pos, gating, temp, ah, al,
                                            out + XU_ELEMS);

    // G4: out[b] = attn_sel[b] @ y[b]   (B = y[b]^T k-major over m, 2-pass)
    gemm_f16_split<<<dim3(DIM/128, SEQ/128, BATCH), 256, GEMM_SMEM>>>(
        ah, al, yTh, yTl, out, nullptr, nullptr, nullptr, nullptr, nullptr, nullptr,
        SEQ, DIM, SEQ, 1.f, smm, (long)768*1024, bnd, 2);
}

// round 10
// speedup vs baseline: 2.8902x; 1.4092x over previous
#include <cuda_runtime.h>
#include <cuda_fp16.h>
#include <math.h>
#include <stdint.h>

// ----------------------------------------------------------------------------
// Problem constants (B=16, N=M=1024, DIM=768, 2 heads)
// ----------------------------------------------------------------------------
#define BATCH 16
#define SEQ   1024
#define DIM   768
#define XU_ELEMS (16LL*1024*768)        // 12,582,912
#define DD     (768*768)                // 589,824

// ----------------------------------------------------------------------------
// Scratch (static device globals — allocation-free)
// ----------------------------------------------------------------------------
__device__ float g_attn[2LL*16*1024*1024];       // raw scores [B,2,N,M]
__device__ float g_pos [1024LL*1024];            // pos_score [N,M]

// fp16 hi/lo split operands (16B-aligned for cp.async / vector access)
__device__ __align__(16) __half g_xh  [16LL*1024*768], g_xl  [16LL*1024*768];
__device__ __align__(16) __half g_UTh [DD],            g_UTl [DD];
__device__ __align__(16) __half g_UTsh[2*DD],          g_UTsl[2*DD];   // UT*diag(S^2), 2 heads
__device__ __align__(16) __half g_wh  [2*DD],          g_wl  [2*DD];   // W = U^T diag(S^2) U
__device__ __align__(16) __half g_yh  [16LL*1024*768], g_yl  [16LL*1024*768];
__device__ __align__(16) __half g_yTh [16LL*768*1024], g_yTl [16LL*768*1024];
__device__ __align__(16) __half g_qh  [2LL*16*1024*768], g_ql[2LL*16*1024*768]; // x@W per head
__device__ __align__(16) __half g_ah  [16LL*1024*1024],  g_al[16LL*1024*1024];  // attn_sel

// ----------------------------------------------------------------------------
// PTX helpers (baseline PTX only — valid on compute_103 non-'a')
// ----------------------------------------------------------------------------
__device__ __forceinline__ uint32_t smem_u32(const void* p) {
    uint32_t a;
    asm("{ .reg .u64 t; cvta.to.shared.u64 t, %1; cvt.u32.u64 %0, t; }" : "=r"(a) : "l"(p));
    return a;
}
#define CP_ASYNC16(dst, src) \
    asm volatile("cp.async.cg.shared.global [%0], [%1], 16;" :: "r"(dst), "l"(src))
#define CP_COMMIT() asm volatile("cp.async.commit_group;")
#define CP_WAIT1()  asm volatile("cp.async.wait_group 1;")

#define LDSM_X4(r0, r1, r2, r3, addr) \
    asm volatile("ldmatrix.sync.aligned.m8n8.x4.shared.b16 {%0,%1,%2,%3}, [%4];" \
                 : "=r"(r0), "=r"(r1), "=r"(r2), "=r"(r3) : "r"(addr))

#define MMA16816(d, a, b) \
    asm volatile("mma.sync.aligned.m16n8k16.row.col.f32.f16.f16.f32 " \
                 "{%0,%1,%2,%3}, {%4,%5,%6,%7}, {%8,%9}, {%0,%1,%2,%3};" \
                 : "+f"((d)[0]), "+f"((d)[1]), "+f"((d)[2]), "+f"((d)[3]) \
                 : "r"((a)[0]), "r"((a)[1]), "r"((a)[2]), "r"((a)[3]), \
                   "r"((b)[0]), "r"((b)[1]))

// ----------------------------------------------------------------------------
// fp16 split helpers
// ----------------------------------------------------------------------------
__device__ __forceinline__ uint32_t hpack2(float a, float b) {
    __half ha = __float2half_rn(a), hb = __float2half_rn(b);
    return ((uint32_t)__half_as_ushort(hb) << 16) | (uint32_t)__half_as_ushort(ha);
}
__device__ __forceinline__ uint32_t hpack_hi2(float a, float b, float& ra, float& rb) {
    __half ha = __float2half_rn(a), hb = __float2half_rn(b);
    ra = a - __half2float(ha);
    rb = b - __half2float(hb);
    return ((uint32_t)__half_as_ushort(hb) << 16) | (uint32_t)__half_as_ushort(ha);
}
__device__ __forceinline__ void store_split(__half* H, __half* L, long off, float a, float b) {
    float ra, rb;
    uint32_t hw = hpack_hi2(a, b, ra, rb);
    *(uint32_t*)(H + off) = hw;
    *(uint32_t*)(L + off) = hpack2(ra, rb);
}

// ----------------------------------------------------------------------------
// Pipelined fp16-split GEMM (mma.sync.m16n8k16, HMMA pipe):
//   C[i,j] = alpha * sum_k (Ahi+Alo)[i,k] * (Bhi+Blo)[j,k]
// npass = 3: hh + lh + hl ; npass = 2: hh + lh (B rounded to fp16).
// A: [M,K] k-major, B: [N,K] k-major. M,N mult of 128, K mult of 64.
// Epilogue: Cf -> fp32; else fp16-split (C1h, C1l).
// CTA 128x128, 8 warps (2x4), warp tile 64x32, 3-stage cp.async pipeline, chunk K=64.
// ----------------------------------------------------------------------------
#define GEMM_SMEM (3 * 32768 + 128)

__global__ __launch_bounds__(256, 2)
void gemm_f16_split(const __half* __restrict__ Ahi, const __half* __restrict__ Alo,
                    const __half* __restrict__ Bhi, const __half* __restrict__ Blo,
                    float* __restrict__ Cf,
                    __half* __restrict__ C1h, __half* __restrict__ C1l,
                    int M, int N, int K, float alpha,
                    long sA, long sB, long sC, int npass)
{
    extern __shared__ char smem_raw[];
    const uint32_t raw_u = smem_u32(smem_raw);
    const uint32_t base  = (raw_u + 127) & ~127u;

    const int tid  = threadIdx.x;
    const int lane = tid & 31;
    const int wid  = tid >> 5;
    const int wm   = wid >> 2;          // 0..1
    const int wn   = wid & 3;           // 0..3

    const int z    = blockIdx.z;
    const int row0 = blockIdx.y * 128;
    const int col0 = blockIdx.x * 128;

    const __half* AP[3] = {Ahi + z * sA, Alo + z * sA, Ahi + z * sA};
    const __half* BP[3] = {Bhi + z * sB, Bhi + z * sB, Blo + z * sB};

    const int kc = K >> 6;              // 64-half chunks per pass
    const int C  = npass * kc;

    // fill assignment: thread covers row r = tid/2, half-row h = tid%2 (32 halfs = 64B)
    const int fr = tid >> 1;
    const int fh = tid & 1;
    const uint32_t fro = (uint32_t)(fr * 128 + fh * 64);

    auto issue = [&](int c) {
        const int s  = c % 3;
        const int p  = c / kc;
        const int kk = (c - p * kc) << 6;
        const __half* ga = AP[p] + (long)(row0 + fr) * K + kk + fh * 32;
        const __half* gb = BP[p] + (long)(col0 + fr) * K + kk + fh * 32;
        const uint32_t sa = base + s * 32768;
        const uint32_t sb = sa + 16384;
        #pragma unroll
        for (int i = 0; i < 4; i++) {
            uint32_t off = fro + i * 16; off ^= (off >> 3) & 0x70;
            CP_ASYNC16(sa + off, ga + i * 8);
        }
        #pragma unroll
        for (int i = 0; i < 4; i++) {
            uint32_t off = fro + i * 16; off ^= (off >> 3) & 0x70;
            CP_ASYNC16(sb + off, gb + i * 8);
        }
        CP_COMMIT();
    };

    float acc[4][4][4] = {};

    issue(0);
    if (C > 1) issue(1);

    for (int c = 0; c < C; c++) {
        CP_WAIT1();
        __syncthreads();
        if (c + 2 < C) issue(c + 2);

        const uint32_t sa = base + (c % 3) * 32768;
        const uint32_t sb = sa + 16384;

        #pragma unroll
        for (int ks = 0; ks < 4; ks++) {
            uint32_t a[4][4];
            #pragma unroll
            for (int mi = 0; mi < 4; mi++) {
                int r  = wm * 64 + mi * 16 + (lane & 15);
                int cb = (ks * 16 + (lane >> 4) * 8) * 2;
                uint32_t off = (uint32_t)(r * 128 + cb); off ^= (off >> 3) & 0x70;
                LDSM_X4(a[mi][0], a[mi][1], a[mi][2], a[mi][3], sa + off);
            }
            uint32_t b[4][2];
            #pragma unroll
            for (int g = 0; g < 2; g++) {
                int n  = wn * 32 + g * 16 + ((lane >> 4) & 1) * 8 + (lane & 7);
                int cb = (ks * 16 + ((lane >> 3) & 1) * 8) * 2;
                uint32_t off = (uint32_t)(n * 128 + cb); off ^= (off >> 3) & 0x70;
                LDSM_X4(b[2*g][0], b[2*g][1], b[2*g+1][0], b[2*g+1][1], sb + off);
            }
            #pragma unroll
            for (int mi = 0; mi < 4; mi++)
                #pragma unroll
                for (int ni = 0; ni < 4; ni++)
                    MMA16816(acc[mi][ni], a[mi], b[ni]);
        }
        __syncthreads();
    }

    // ------------------------------------------------------------------ epilogue
    const long cb0 = (long)z * sC;
    #pragma unroll
    for (int mi = 0; mi < 4; mi++) {
        #pragma unroll
        for (int ni = 0; ni < 4; ni++) {
            const int r  = row0 + wm * 64 + mi * 16 + (lane >> 2);
            const int cc = col0 + wn * 32 + ni * 8 + (lane & 3) * 2;
            const long o0 = cb0 + (long)r * N + cc;
            const long o1 = o0 + 8L * N;
            const float* av = acc[mi][ni];
            if (Cf) {
                *(float2*)(Cf + o0) = make_float2(av[0] * alpha, av[1] * alpha);
                *(float2*)(Cf + o1) = make_float2(av[2] * alpha, av[3] * alpha);
            } else {
                store_split(C1h, C1l, o0, av[0], av[1]);
                store_split(C1h, C1l, o1, av[2], av[3]);
            }
        }
    }
}

// ----------------------------------------------------------------------------
// Conversion kernels (fp32 -> fp16 hi/lo split)
// ----------------------------------------------------------------------------
__global__ void k_split(const float* __restrict__ in, __half* __restrict__ hi,
                        __half* __restrict__ lo, long n4)
{
    long i = (long)blockIdx.x * blockDim.x + threadIdx.x;
    if (i >= n4) return;
    float4 v = ((const float4*)in)[i];
    float r0, r1, r2, r3;
    uint32_t h01 = hpack_hi2(v.x, v.y, r0, r1);
    uint32_t h23 = hpack_hi2(v.z, v.w, r2, r3);
    ((uint2*)hi)[i] = make_uint2(h01, h23);
    ((uint2*)lo)[i] = make_uint2(hpack2(r0, r1), hpack2(r2, r3));
}

// transpose + split: in [R, Cc] fp32 -> out [Cc, R] fp16 hi/lo, batched on z
__global__ void k_split_T(const float* __restrict__ in, __half* __restrict__ hi,
                          __half* __restrict__ lo, int R, int Cc, long sIn, long sOut)
{
    __shared__ float t[32][33];
    const int z  = blockIdx.z;
    const int c0 = blockIdx.x * 32, r0 = blockIdx.y * 32;
    const float* ip = in + (long)z * sIn;
    const int tx = threadIdx.x & 31, ty = threadIdx.x >> 5;
    #pragma unroll
    for (int rr = ty; rr < 32; rr += 8)
        t[rr][tx] = ip[(long)(r0 + rr) * Cc + c0 + tx];
    __syncthreads();
    #pragma unroll
    for (int cc = ty; cc < 32; cc += 8) {
        float v = t[tx][cc];
        __half h = __float2half_rn(v);
        float rl = v - __half2float(h);
        long o = (long)z * sOut + (long)(c0 + cc) * R + r0 + tx;
        hi[o] = h;
        lo[o] = __float2half_rn(rl);
    }
}

// U prep: UT = U^T split, and UTs[h] = U^T * diag(S_h^2) split (both heads).
// out[i,k] = U[k,i] (* d_k). 768x768.
__global__ void k_prep_U(const float* __restrict__ U,
                         const float* __restrict__ S1, const float* __restrict__ S2,
                         __half* __restrict__ uth, __half* __restrict__ utl,
                         __half* __restrict__ utsh, __half* __restrict__ utsl)
{
    __shared__ float t[32][33];
    const int c0 = blockIdx.x * 32, r0 = blockIdx.y * 32;
    const int tx = threadIdx.x & 31, ty = threadIdx.x >> 5;
    #pragma unroll
    for (int rr = ty; rr < 32; rr += 8)
        t[rr][tx] = U[(long)(r0 + rr) * 768 + c0 + tx];
    __syncthreads();
    const int k = r0 + tx;                       // input row = spectral index
    const float s1 = S1[k], s2 = S2[k];
    const float d1 = s1 * s1, d2 = s2 * s2;
    #pragma unroll
    for (int cc = ty; cc < 32; cc += 8) {
        float v = t[tx][cc];                     // = U[k, c0+cc]
        const long o = (long)(c0 + cc) * 768 + k;
        __half h = __float2half_rn(v);
        uth[o] = h; utl[o] = __float2half_rn(v - __half2float(h));
        float v1 = v * d1;
        __half h1 = __float2half_rn(v1);
        utsh[o] = h1; utsl[o] = __float2half_rn(v1 - __half2float(h1));
        float v2 = v * d2;
        __half h2 = __float2half_rn(v2);
        utsh[DD + o] = h2; utsl[DD + o] = __float2half_rn(v2 - __half2float(h2));
    }
}

// ----------------------------------------------------------------------------
// Block reductions (256 threads, 8 warps)
// ----------------------------------------------------------------------------
__device__ __forceinline__ float block_sum(float v, float* red) {
    #pragma unroll
    for (int o = 16; o; o >>= 1) v += __shfl_xor_sync(0xffffffffu, v, o);
    __syncthreads();
    if ((threadIdx.x & 31) == 0) red[threadIdx.x >> 5] = v;
    __syncthreads();
    float r = red[0];
    #pragma unroll
    for (int w = 1; w < 8; w++) r += red[w];
    return r;
}
__device__ __forceinline__ float block_max(float v, float* red) {
    #pragma unroll
    for (int o = 16; o; o >>= 1) v = fmaxf(v, __shfl_xor_sync(0xffffffffu, v, o));
    __syncthreads();
    if ((threadIdx.x & 31) == 0) red[threadIdx.x >> 5] = v;
    __syncthreads();
    float r = red[0];
    #pragma unroll
    for (int w = 1; w < 8; w++) r = fmaxf(r, red[w]);
    return r;
}

// ----------------------------------------------------------------------------
// pos_score softmax
// ----------------------------------------------------------------------------
__global__ void pos_softmax(const float* __restrict__ coords, const float* __restrict__ pe,
                            float* __restrict__ pos)
{
    const int n   = blockIdx.x;
    const int tid = threadIdx.x;
    __shared__ float red[8];
    __shared__ float w[6];
    if (tid < 6) w[tid] = pe[n * 6 + tid];
    __syncthreads();

    float p[4];
    #pragma unroll
    for (int i = 0; i < 4; i++) {
        const float* c = coords + ((long)n * SEQ + tid * 4 + i) * 6;
        p[i] = w[0]*c[0] + w[1]*c[1] + w[2]*c[2] + w[3]*c[3] + w[4]*c[4] + w[5]*c[5];
    }
    float mx = fmaxf(fmaxf(p[0], p[1]), fmaxf(p[2], p[3]));
    mx = block_max(mx, red);
    float e[4], sum = 0.f;
    #pragma unroll
    for (int i = 0; i < 4; i++) { e[i] = expf(p[i] - mx); sum += e[i]; }
    sum = block_sum(sum, red);
    float inv = 1.f / sum;
    *(float4*)(pos + (long)n * SEQ + tid * 4) = make_float4(e[0]*inv, e[1]*inv, e[2]*inv, e[3]*inv);
}

// ----------------------------------------------------------------------------
// FUSED: softmax + gating mixture + entropy + routing + head-select + fp16 split.
// One block per (b,n): processes BOTH heads' score rows, routes, and writes
// only the selected attn row (fp16 hi/lo) + heat_map. No fp32 attn writeback.
// ----------------------------------------------------------------------------
__global__ void softmax_route_fused(const float* __restrict__ scores,
                                    const float* __restrict__ pos,
                                    const float* __restrict__ gating,
                                    const float* __restrict__ temp,
                                    __half* __restrict__ ah, __half* __restrict__ al,
                                    float* __restrict__ heat)
{
    const int r   = blockIdx.x;                 // (b, n)
    const int b   = r >> 10, n = r & 1023;
    const int tid = threadIdx.x;
    __shared__ float red[8];

    const float* row0 = scores + ((long)(b * 2 + 0) * SEQ + n) * SEQ;
    const float* row1 = scores + ((long)(b * 2 + 1) * SEQ + n) * SEQ;
    const float* q    = pos + (long)n * SEQ;

    float4 v0 = *(const float4*)(row0 + tid * 4);
    float4 v1 = *(const float4*)(row1 + tid * 4);
    float4 qv = *(const float4*)(q + tid * 4);

    float mx0 = fmaxf(fmaxf(v0.x, v0.y), fmaxf(v0.z, v0.w));
    float mx1 = fmaxf(fmaxf(v1.x, v1.y), fmaxf(v1.z, v1.w));
    mx0 = block_max(mx0, red);
    mx1 = block_max(mx1, red);

    float4 e0, e1;
    e0.x = expf(v0.x - mx0); e0.y = expf(v0.y - mx0);
    e0.z = expf(v0.z - mx0); e0.w = expf(v0.w - mx0);
    e1.x = expf(v1.x - mx1); e1.y = expf(v1.y - mx1);
    e1.z = expf(v1.z - mx1); e1.w = expf(v1.w - mx1);
    float sum0 = block_sum(e0.x + e0.y + e0.z + e0.w, red);
    float sum1 = block_sum(e1.x + e1.y + e1.z + e1.w, red);

    const float g    = 1.f / (1.f + expf(-gating[0]));
    const float omg0 = (1.f - g) / sum0;
    const float omg1 = (1.f - g) / sum1;

    float4 a0, a1;
    a0.x = omg0*e0.x + g*qv.x; a0.y = omg0*e0.y + g*qv.y;
    a0.z = omg0*e0.z + g*qv.z; a0.w = omg0*e0.w + g*qv.w;
    a1.x = omg1*e1.x + g*qv.x; a1.y = omg1*e1.y + g*qv.y;
    a1.z = omg1*e1.z + g*qv.z; a1.w = omg1*e1.w + g*qv.w;

    float ep0 = -(a0.x * logf(a0.x + 1e-8f) + a0.y * logf(a0.y + 1e-8f)
                + a0.z * logf(a0.z + 1e-8f) + a0.w * logf(a0.w + 1e-8f));
    float ep1 = -(a1.x * logf(a1.x + 1e-8f) + a1.y * logf(a1.y + 1e-8f)
                + a1.z * logf(a1.z + 1e-8f) + a1.w * logf(a1.w + 1e-8f));
    ep0 = block_sum(ep0, red);
    ep1 = block_sum(ep1, red);

    const float t  = temp[0];
    const float h0 = 2.f - 2.f / (1.f + expf(-t * ep0));
    const float h1 = 2.f - 2.f / (1.f + expf(-t * ep1));
    const int   s  = (h0 >= h1) ? 0 : 1;

    if (tid == 0) heat[r] = s ? h1 : h0;

    const float4 a = s ? a1 : a0;
    float r0a, r1a, r2a, r3a;
    uint32_t h01 = hpack_hi2(a.x, a.y, r0a, r1a);
    uint32_t h23 = hpack_hi2(a.z, a.w, r2a, r3a);
    const long o = (long)r * (SEQ / 4) + tid;
    ((uint2*)ah)[o] = make_uint2(h01, h23);
    ((uint2*)al)[o] = make_uint2(hpack2(r0a, r1a), hpack2(r2a, r3a));
}

// ----------------------------------------------------------------------------
// kernel_launch
// Inputs: 0:x 1:y 2:coords 3:U 4:S1 5:S2 6:gating 7:temp 8:pos_emb
// Output: out [B,N,DIM] (12,582,912 f32) then heat_map [B,N,1] (16,384 f32)
// ----------------------------------------------------------------------------
extern "C" void kernel_launch(void* const* d_in, const int* in_sizes, int n_in,
                              void* d_out, int out_size)
{
    const float* x      = (const float*)d_in[0];
    const float* y      = (const float*)d_in[1];
    const float* coords = (const float*)d_in[2];
    const float* U      = (const float*)d_in[3];
    const float* S1     = (const float*)d_in[4];
    const float* S2     = (const float*)d_in[5];
    const float* gating = (const float*)d_in[6];
    const float* temp   = (const float*)d_in[7];
    const float* pe     = (const float*)d_in[8];
    float* out = (float*)d_out;

    float *attn, *pos;
    __half *xh, *xl, *UTh, *UTl, *UTsh, *UTsl, *wh, *wl;
    __half *yh, *yl, *yTh, *yTl, *qh, *ql, *ah, *al;
    cudaGetSymbolAddress((void**)&attn, g_attn);
    cudaGetSymbolAddress((void**)&pos,  g_pos);
    cudaGetSymbolAddress((void**)&xh,   g_xh);    cudaGetSymbolAddress((void**)&xl,   g_xl);
    cudaGetSymbolAddress((void**)&UTh,  g_UTh);   cudaGetSymbolAddress((void**)&UTl,  g_UTl);
    cudaGetSymbolAddress((void**)&UTsh, g_UTsh);  cudaGetSymbolAddress((void**)&UTsl, g_UTsl);
    cudaGetSymbolAddress((void**)&wh,   g_wh);    cudaGetSymbolAddress((void**)&wl,   g_wl);
    cudaGetSymbolAddress((void**)&yh,   g_yh);    cudaGetSymbolAddress((void**)&yl,   g_yl);
    cudaGetSymbolAddress((void**)&yTh,  g_yTh);   cudaGetSymbolAddress((void**)&yTl,  g_yTl);
    cudaGetSymbolAddress((void**)&qh,   g_qh);    cudaGetSymbolAddress((void**)&ql,   g_ql);
    cudaGetSymbolAddress((void**)&ah,   g_ah);    cudaGetSymbolAddress((void**)&al,   g_al);

    cudaFuncSetAttribute(gemm_f16_split,
                         cudaFuncAttributeMaxDynamicSharedMemorySize, GEMM_SMEM);

    const float scale = 1.f / sqrtf((float)DIM);
    const long bnd = (long)SEQ * DIM;   // per-batch stride of x/y slices
    const long smm = (long)SEQ * SEQ;   // one score plane

    // input splits / prep
    k_split<<<(int)((XU_ELEMS/4 + 255)/256), 256>>>(x, xh, xl, XU_ELEMS/4);
    k_split<<<(int)((XU_ELEMS/4 + 255)/256), 256>>>(y, yh, yl, XU_ELEMS/4);
    k_split_T<<<dim3(768/32, 1024/32, BATCH), 256>>>(y, yTh, yTl, 1024, 768,
                                                     bnd, (long)768*1024);
    k_prep_U<<<dim3(768/32, 768/32), 256>>>(U, S1, S2, UTh, UTl, UTsh, UTsl);
    pos_softmax<<<SEQ, 256>>>(coords, pe, pos);

    // W[h] = (U^T diag(S_h^2)) @ (U^T)^T  -> symmetric 768x768, fp16-split (3-pass)
    gemm_f16_split<<<dim3(768/128, 768/128, 2), 256, GEMM_SMEM>>>(
        UTsh, UTsl, UTh, UTl, nullptr, wh, wl,
        768, 768, 768, 1.f, DD, 0, DD, 3);

    // q[h] = x @ W[h]  (W symmetric; B = W k-major). 2-pass, fp16-split out.
    gemm_f16_split<<<dim3(768/128, (BATCH*SEQ)/128, 2), 256, GEMM_SMEM>>>(
        xh, xl, wh, wl, nullptr, qh, ql,
        BATCH*SEQ, 768, 768, 1.f, 0, DD, XU_ELEMS, 2);

    // G3: scores[b,h] = scale * q[h][b] @ y[b]^T  (batched over b per head, 2-pass)
    gemm_f16_split<<<dim3(SEQ/128, SEQ/128, BATCH), 256, GEMM_SMEM>>>(
        qh,            ql,            yh, yl, attn,       nullptr, nullptr,
        SEQ, SEQ, DIM, scale, bnd, bnd, 2*smm, 2);
    gemm_f16_split<<<dim3(SEQ/128, SEQ/128, BATCH), 256, GEMM_SMEM>>>(
        qh + XU_ELEMS, ql + XU_ELEMS, yh, yl, attn + smm, nullptr, nullptr,
        SEQ, SEQ, DIM, scale, bnd, bnd, 2*smm, 2);

    // fused softmax + mixture + entropy + route + gather-split + heat
    softmax_route_fused<<<BATCH*SEQ, 256>>>(attn, pos, gating, temp, ah, al,
                                            out + XU_ELEMS);

    // G4: out[b] = attn_sel[b] @ y[b]   (B = y[b]^T k-major over m, 2-pass)
    gemm_f16_split<<<dim3(DIM/128, SEQ/128, BATCH), 256, GEMM_SMEM>>>(
        ah, al, yTh, yTl, out, nullptr, nullptr,
        SEQ, DIM, SEQ, 1.f, smm, (long)768*1024, bnd, 2);
}

// round 13
// speedup vs baseline: 3.9863x; 1.3793x over previous
#include <cuda_runtime.h>
#include <cuda_fp16.h>
#include <math.h>
#include <stdint.h>

// ----------------------------------------------------------------------------
// Problem constants (B=16, N=M=1024, DIM=768, 2 heads)
// ----------------------------------------------------------------------------
#define BATCH 16
#define SEQ   1024
#define DIM   768
#define XU_ELEMS (16LL*1024*768)        // 12,582,912
#define DD     (768*768)                // 589,824

// ----------------------------------------------------------------------------
// Scratch (static device globals — allocation-free)
// ----------------------------------------------------------------------------
__device__ float g_attn[2LL*16*1024*1024];       // raw scores [B,2,N,M]
__device__ float g_pos [1024LL*1024];            // pos_score [N,M]

// fp16 operands (16B-aligned for cp.async / vector access)
__device__ __align__(16) __half g_xh  [16LL*1024*768], g_xl  [16LL*1024*768];
__device__ __align__(16) __half g_UTh [DD],            g_UTl [DD];
__device__ __align__(16) __half g_UTsh[2*DD],          g_UTsl[2*DD];   // UT*diag(S^2), 2 heads
__device__ __align__(16) __half g_wh  [2*DD],          g_wl  [2*DD];   // W = U^T diag(S^2) U
__device__ __align__(16) __half g_yh  [16LL*1024*768];                 // y (hi only)
__device__ __align__(16) __half g_yTh [16LL*768*1024];                 // y^T (hi only)
__device__ __align__(16) __half g_qh  [2LL*16*1024*768];               // x@W per head (hi only)
__device__ __align__(16) __half g_ah  [16LL*1024*1024];                // attn_sel (hi only)

// ----------------------------------------------------------------------------
// PTX helpers (baseline PTX only — valid on compute_103 non-'a')
// ----------------------------------------------------------------------------
__device__ __forceinline__ uint32_t smem_u32(const void* p) {
    uint32_t a;
    asm("{ .reg .u64 t; cvta.to.shared.u64 t, %1; cvt.u32.u64 %0, t; }" : "=r"(a) : "l"(p));
    return a;
}
#define CP_ASYNC16(dst, src) \
    asm volatile("cp.async.cg.shared.global [%0], [%1], 16;" :: "r"(dst), "l"(src))
#define CP_COMMIT() asm volatile("cp.async.commit_group;")
#define CP_WAIT1()  asm volatile("cp.async.wait_group 1;")

#define LDSM_X4(r0, r1, r2, r3, addr) \
    asm volatile("ldmatrix.sync.aligned.m8n8.x4.shared.b16 {%0,%1,%2,%3}, [%4];" \
                 : "=r"(r0), "=r"(r1), "=r"(r2), "=r"(r3) : "r"(addr))

#define MMA16816(d, a, b) \
    asm volatile("mma.sync.aligned.m16n8k16.row.col.f32.f16.f16.f32 " \
                 "{%0,%1,%2,%3}, {%4,%5,%6,%7}, {%8,%9}, {%0,%1,%2,%3};" \
                 : "+f"((d)[0]), "+f"((d)[1]), "+f"((d)[2]), "+f"((d)[3]) \
                 : "r"((a)[0]), "r"((a)[1]), "r"((a)[2]), "r"((a)[3]), \
                   "r"((b)[0]), "r"((b)[1]))

// ----------------------------------------------------------------------------
// fp16 split helpers
// ----------------------------------------------------------------------------
__device__ __forceinline__ uint32_t hpack2(float a, float b) {
    __half ha = __float2half_rn(a), hb = __float2half_rn(b);
    return ((uint32_t)__half_as_ushort(hb) << 16) | (uint32_t)__half_as_ushort(ha);
}
__device__ __forceinline__ uint32_t hpack_hi2(float a, float b, float& ra, float& rb) {
    __half ha = __float2half_rn(a), hb = __float2half_rn(b);
    ra = a - __half2float(ha);
    rb = b - __half2float(hb);
    return ((uint32_t)__half_as_ushort(hb) << 16) | (uint32_t)__half_as_ushort(ha);
}
__device__ __forceinline__ void store_split(__half* H, __half* L, long off, float a, float b) {
    float ra, rb;
    uint32_t hw = hpack_hi2(a, b, ra, rb);
    *(uint32_t*)(H + off) = hw;
    *(uint32_t*)(L + off) = hpack2(ra, rb);
}

// ----------------------------------------------------------------------------
// Pipelined fp16-split GEMM (mma.sync.m16n8k16, HMMA pipe):
//   C[i,j] = alpha * sum_k A[i,k] * B[j,k]
// npass = 3: (Ahi+Alo)@(Bhi) + Ahi@Blo ; npass = 2: (Ahi+Alo)@Bhi ; npass = 1: Ahi@Bhi.
// A: [M,K] k-major, B: [N,K] k-major. M,N mult of 128, K mult of 64.
// Epilogue: Cf -> fp32; else if C1l -> fp16 split (C1h,C1l); else fp16 hi-only C1h.
// CTA 128x128, 8 warps (2x4), warp tile 64x32, 3-stage cp.async pipeline, chunk K=64.
// ----------------------------------------------------------------------------
#define GEMM_SMEM (3 * 32768 + 128)

__global__ __launch_bounds__(256, 2)
void gemm_f16_split(const __half* __restrict__ Ahi, const __half* __restrict__ Alo,
                    const __half* __restrict__ Bhi, const __half* __restrict__ Blo,
                    float* __restrict__ Cf,
                    __half* __restrict__ C1h, __half* __restrict__ C1l,
                    int M, int N, int K, float alpha,
                    long sA, long sB, long sC, int npass)
{
    extern __shared__ char smem_raw[];
    const uint32_t raw_u = smem_u32(smem_raw);
    const uint32_t base  = (raw_u + 127) & ~127u;

    const int tid  = threadIdx.x;
    const int lane = tid & 31;
    const int wid  = tid >> 5;
    const int wm   = wid >> 2;          // 0..1
    const int wn   = wid & 3;           // 0..3

    const int z    = blockIdx.z;
    const int row0 = blockIdx.y * 128;
    const int col0 = blockIdx.x * 128;

    const __half* AP[3] = {Ahi + z * sA, Alo + z * sA, Ahi + z * sA};
    const __half* BP[3] = {Bhi + z * sB, Bhi + z * sB, Blo + z * sB};

    const int kc = K >> 6;              // 64-half chunks per pass
    const int C  = npass * kc;

    // fill assignment: thread covers row r = tid/2, half-row h = tid%2 (32 halfs = 64B)
    const int fr = tid >> 1;
    const int fh = tid & 1;
    const uint32_t fro = (uint32_t)(fr * 128 + fh * 64);

    auto issue = [&](int c) {
        const int s  = c % 3;
        const int p  = c / kc;
        const int kk = (c - p * kc) << 6;
        const __half* ga = AP[p] + (long)(row0 + fr) * K + kk + fh * 32;
        const __half* gb = BP[p] + (long)(col0 + fr) * K + kk + fh * 32;
        const uint32_t sa = base + s * 32768;
        const uint32_t sb = sa + 16384;
        #pragma unroll
        for (int i = 0; i < 4; i++) {
            uint32_t off = fro + i * 16; off ^= (off >> 3) & 0x70;
            CP_ASYNC16(sa + off, ga + i * 8);
        }
        #pragma unroll
        for (int i = 0; i < 4; i++) {
            uint32_t off = fro + i * 16; off ^= (off >> 3) & 0x70;
            CP_ASYNC16(sb + off, gb + i * 8);
        }
        CP_COMMIT();
    };

    float acc[4][4][4] = {};

    issue(0);
    if (C > 1) issue(1);

    for (int c = 0; c < C; c++) {
        CP_WAIT1();
        __syncthreads();
        if (c + 2 < C) issue(c + 2);

        const uint32_t sa = base + (c % 3) * 32768;
        const uint32_t sb = sa + 16384;

        #pragma unroll
        for (int ks = 0; ks < 4; ks++) {
            uint32_t a[4][4];
            #pragma unroll
            for (int mi = 0; mi < 4; mi++) {
                int r  = wm * 64 + mi * 16 + (lane & 15);
                int cb = (ks * 16 + (lane >> 4) * 8) * 2;
                uint32_t off = (uint32_t)(r * 128 + cb); off ^= (off >> 3) & 0x70;
                LDSM_X4(a[mi][0], a[mi][1], a[mi][2], a[mi][3], sa + off);
            }
            uint32_t b[4][2];
            #pragma unroll
            for (int g = 0; g < 2; g++) {
                int n  = wn * 32 + g * 16 + ((lane >> 4) & 1) * 8 + (lane & 7);
                int cb = (ks * 16 + ((lane >> 3) & 1) * 8) * 2;
                uint32_t off = (uint32_t)(n * 128 + cb); off ^= (off >> 3) & 0x70;
                LDSM_X4(b[2*g][0], b[2*g][1], b[2*g+1][0], b[2*g+1][1], sb + off);
            }
            #pragma unroll
            for (int mi = 0; mi < 4; mi++)
                #pragma unroll
                for (int ni = 0; ni < 4; ni++)
                    MMA16816(acc[mi][ni], a[mi], b[ni]);
        }
        __syncthreads();
    }

    // ------------------------------------------------------------------ epilogue
    const long cb0 = (long)z * sC;
    #pragma unroll
    for (int mi = 0; mi < 4; mi++) {
        #pragma unroll
        for (int ni = 0; ni < 4; ni++) {
            const int r  = row0 + wm * 64 + mi * 16 + (lane >> 2);
            const int cc = col0 + wn * 32 + ni * 8 + (lane & 3) * 2;
            const long o0 = cb0 + (long)r * N + cc;
            const long o1 = o0 + 8L * N;
            const float* av = acc[mi][ni];
            if (Cf) {
                *(float2*)(Cf + o0) = make_float2(av[0] * alpha, av[1] * alpha);
                *(float2*)(Cf + o1) = make_float2(av[2] * alpha, av[3] * alpha);
            } else if (C1l) {
                store_split(C1h, C1l, o0, av[0] * alpha, av[1] * alpha);
                store_split(C1h, C1l, o1, av[2] * alpha, av[3] * alpha);
            } else {
                *(uint32_t*)(C1h + o0) = hpack2(av[0] * alpha, av[1] * alpha);
                *(uint32_t*)(C1h + o1) = hpack2(av[2] * alpha, av[3] * alpha);
            }
        }
    }
}

// ----------------------------------------------------------------------------
// Conversion kernels
// ----------------------------------------------------------------------------
// fp32 -> fp16 hi/lo split (for x: A-side of 2-pass xW)
__global__ void k_split(const float* __restrict__ in, __half* __restrict__ hi,
                        __half* __restrict__ lo, long n4)
{
    long i = (long)blockIdx.x * blockDim.x + threadIdx.x;
    if (i >= n4) return;
    float4 v = ((const float4*)in)[i];
    float r0, r1, r2, r3;
    uint32_t h01 = hpack_hi2(v.x, v.y, r0, r1);
    uint32_t h23 = hpack_hi2(v.z, v.w, r2, r3);
    ((uint2*)hi)[i] = make_uint2(h01, h23);
    ((uint2*)lo)[i] = make_uint2(hpack2(r0, r1), hpack2(r2, r3));
}

// y dual convert: read y [SEQ, DIM] once per batch; write straight fp16 (yh)
// and transposed fp16 (yTh [DIM, SEQ]). hi only (lo unused in 1-pass GEMMs).
__global__ void k_split_y_dual(const float* __restrict__ y,
                               __half* __restrict__ yh, __half* __restrict__ yTh)
{
    __shared__ float t[32][33];
    const int z  = blockIdx.z;
    const int c0 = blockIdx.x * 32, r0 = blockIdx.y * 32;
    const float* ip = y + (long)z * SEQ * DIM;
    const int tx = threadIdx.x & 31, ty = threadIdx.x >> 5;
    #pragma unroll
    for (int rr = ty; rr < 32; rr += 8) {
        float v = ip[(long)(r0 + rr) * DIM + c0 + tx];
        t[rr][tx] = v;
        yh[(long)z * SEQ * DIM + (long)(r0 + rr) * DIM + c0 + tx] = __float2half_rn(v);
    }
    __syncthreads();
    #pragma unroll
    for (int cc = ty; cc < 32; cc += 8) {
        float v = t[tx][cc];
        yTh[(long)z * DIM * SEQ + (long)(c0 + cc) * SEQ + r0 + tx] = __float2half_rn(v);
    }
}

// U prep: UT = U^T split, and UTs[h] = U^T * diag(S_h^2) split (both heads).
__global__ void k_prep_U(const float* __restrict__ U,
                         const float* __restrict__ S1, const float* __restrict__ S2,
                         __half* __restrict__ uth, __half* __restrict__ utl,
                         __half* __restrict__ utsh, __half* __restrict__ utsl)
{
    __shared__ float t[32][33];
    const int c0 = blockIdx.x * 32, r0 = blockIdx.y * 32;
    const int tx = threadIdx.x & 31, ty = threadIdx.x >> 5;
    #pragma unroll
    for (int rr = ty; rr < 32; rr += 8)
        t[rr][tx] = U[(long)(r0 + rr) * 768 + c0 + tx];
    __syncthreads();
    const int k = r0 + tx;                       // input row = spectral index
    const float s1 = S1[k], s2 = S2[k];
    const float d1 = s1 * s1, d2 = s2 * s2;
    #pragma unroll
    for (int cc = ty; cc < 32; cc += 8) {
        float v = t[tx][cc];                     // = U[k, c0+cc]
        const long o = (long)(c0 + cc) * 768 + k;
        __half h = __float2half_rn(v);
        uth[o] = h; utl[o] = __float2half_rn(v - __half2float(h));
        float v1 = v * d1;
        __half h1 = __float2half_rn(v1);
        utsh[o] = h1; utsl[o] = __float2half_rn(v1 - __half2float(h1));
        float v2 = v * d2;
        __half h2 = __float2half_rn(v2);
        utsh[DD + o] = h2; utsl[DD + o] = __float2half_rn(v2 - __half2float(h2));
    }
}

// ----------------------------------------------------------------------------
// Block reductions (256 threads, 8 warps)
// ----------------------------------------------------------------------------
__device__ __forceinline__ float block_sum(float v, float* red) {
    #pragma unroll
    for (int o = 16; o; o >>= 1) v += __shfl_xor_sync(0xffffffffu, v, o);
    __syncthreads();
    if ((threadIdx.x & 31) == 0) red[threadIdx.x >> 5] = v;
    __syncthreads();
    float r = red[0];
    #pragma unroll
    for (int w = 1; w < 8; w++) r += red[w];
    return r;
}
__device__ __forceinline__ float block_max(float v, float* red) {
    #pragma unroll
    for (int o = 16; o; o >>= 1) v = fmaxf(v, __shfl_xor_sync(0xffffffffu, v, o));
    __syncthreads();
    if ((threadIdx.x & 31) == 0) red[threadIdx.x >> 5] = v;
    __syncthreads();
    float r = red[0];
    #pragma unroll
    for (int w = 1; w < 8; w++) r = fmaxf(r, red[w]);
    return r;
}

// ----------------------------------------------------------------------------
// pos_score softmax
// ----------------------------------------------------------------------------
__global__ void pos_softmax(const float* __restrict__ coords, const float* __restrict__ pe,
                            float* __restrict__ pos)
{
    const int n   = blockIdx.x;
    const int tid = threadIdx.x;
    __shared__ float red[8];
    __shared__ float w[6];
    if (tid < 6) w[tid] = pe[n * 6 + tid];
    __syncthreads();

    float p[4];
    #pragma unroll
    for (int i = 0; i < 4; i++) {
        const float* c = coords + ((long)n * SEQ + tid * 4 + i) * 6;
        p[i] = w[0]*c[0] + w[1]*c[1] + w[2]*c[2] + w[3]*c[3] + w[4]*c[4] + w[5]*c[5];
    }
    float mx = fmaxf(fmaxf(p[0], p[1]), fmaxf(p[2], p[3]));
    mx = block_max(mx, red);
    float e[4], sum = 0.f;
    #pragma unroll
    for (int i = 0; i < 4; i++) { e[i] = expf(p[i] - mx); sum += e[i]; }
    sum = block_sum(sum, red);
    float inv = 1.f / sum;
    *(float4*)(pos + (long)n * SEQ + tid * 4) = make_float4(e[0]*inv, e[1]*inv, e[2]*inv, e[3]*inv);
}

// ----------------------------------------------------------------------------
// FUSED: softmax + gating mixture + entropy + routing + head-select + fp16.
// One block per (b,n): processes BOTH heads' score rows, routes, and writes
// only the selected attn row (fp16 hi) + heat_map. No fp32 attn writeback.
// ----------------------------------------------------------------------------
__global__ void softmax_route_fused(const float* __restrict__ scores,
                                    const float* __restrict__ pos,
                                    const float* __restrict__ gating,
                                    const float* __restrict__ temp,
                                    __half* __restrict__ ah,
                                    float* __restrict__ heat)
{
    const int r   = blockIdx.x;                 // (b, n)
    const int b   = r >> 10, n = r & 1023;
    const int tid = threadIdx.x;
    __shared__ float red[8];

    const float* row0 = scores + ((long)(b * 2 + 0) * SEQ + n) * SEQ;
    const float* row1 = scores + ((long)(b * 2 + 1) * SEQ + n) * SEQ;
    const float* q    = pos + (long)n * SEQ;

    float4 v0 = *(const float4*)(row0 + tid * 4);
    float4 v1 = *(const float4*)(row1 + tid * 4);
    float4 qv = *(const float4*)(q + tid * 4);

    float mx0 = fmaxf(fmaxf(v0.x, v0.y), fmaxf(v0.z, v0.w));
    float mx1 = fmaxf(fmaxf(v1.x, v1.y), fmaxf(v1.z, v1.w));
    mx0 = block_max(mx0, red);
    mx1 = block_max(mx1, red);

    float4 e0, e1;
    e0.x = expf(v0.x - mx0); e0.y = expf(v0.y - mx0);
    e0.z = expf(v0.z - mx0); e0.w = expf(v0.w - mx0);
    e1.x = expf(v1.x - mx1); e1.y = expf(v1.y - mx1);
    e1.z = expf(v1.z - mx1); e1.w = expf(v1.w - mx1);
    float sum0 = block_sum(e0.x + e0.y + e0.z + e0.w, red);
    float sum1 = block_sum(e1.x + e1.y + e1.z + e1.w, red);

    const float g    = 1.f / (1.f + expf(-gating[0]));
    const float omg0 = (1.f - g) / sum0;
    const float omg1 = (1.f - g) / sum1;

    float4 a0, a1;
    a0.x = omg0*e0.x + g*qv.x; a0.y = omg0*e0.y + g*qv.y;
    a0.z = omg0*e0.z + g*qv.z; a0.w = omg0*e0.w + g*qv.w;
    a1.x = omg1*e1.x + g*qv.x; a1.y = omg1*e1.y + g*qv.y;
    a1.z = omg1*e1.z + g*qv.z; a1.w = omg1*e1.w + g*qv.w;

    float ep0 = -(a0.x * logf(a0.x + 1e-8f) + a0.y * logf(a0.y + 1e-8f)
                + a0.z * logf(a0.z + 1e-8f) + a0.w * logf(a0.w + 1e-8f));
    float ep1 = -(a1.x * logf(a1.x + 1e-8f) + a1.y * logf(a1.y + 1e-8f)
                + a1.z * logf(a1.z + 1e-8f) + a1.w * logf(a1.w + 1e-8f));
    ep0 = block_sum(ep0, red);
    ep1 = block_sum(ep1, red);

    const float t  = temp[0];
    const float h0 = 2.f - 2.f / (1.f + expf(-t * ep0));
    const float h1 = 2.f - 2.f / (1.f + expf(-t * ep1));
    const int   s  = (h0 >= h1) ? 0 : 1;

    if (tid == 0) heat[r] = s ? h1 : h0;

    const float4 a = s ? a1 : a0;
    const long o = (long)r * (SEQ / 4) + tid;
    ((uint2*)ah)[o] = make_uint2(hpack2(a.x, a.y), hpack2(a.z, a.w));
}

// ----------------------------------------------------------------------------
// kernel_launch
// Inputs: 0:x 1:y 2:coords 3:U 4:S1 5:S2 6:gating 7:temp 8:pos_emb
// Output: out [B,N,DIM] (12,582,912 f32) then heat_map [B,N,1] (16,384 f32)
// ----------------------------------------------------------------------------
extern "C" void kernel_launch(void* const* d_in, const int* in_sizes, int n_in,
                              void* d_out, int out_size)
{
    const float* x      = (const float*)d_in[0];
    const float* y      = (const float*)d_in[1];
    const float* coords = (const float*)d_in[2];
    const float* U      = (const float*)d_in[3];
    const float* S1     = (const float*)d_in[4];
    const float* S2     = (const float*)d_in[5];
    const float* gating = (const float*)d_in[6];
    const float* temp   = (const float*)d_in[7];
    const float* pe     = (const float*)d_in[8];
    float* out = (float*)d_out;

    float *attn, *pos;
    __half *xh, *xl, *UTh, *UTl, *UTsh, *UTsl, *wh, *wl;
    __half *yh, *yTh, *qh, *ah;
    cudaGetSymbolAddress((void**)&attn, g_attn);
    cudaGetSymbolAddress((void**)&pos,  g_pos);
    cudaGetSymbolAddress((void**)&xh,   g_xh);    cudaGetSymbolAddress((void**)&xl,   g_xl);
    cudaGetSymbolAddress((void**)&UTh,  g_UTh);   cudaGetSymbolAddress((void**)&UTl,  g_UTl);
    cudaGetSymbolAddress((void**)&UTsh, g_UTsh);  cudaGetSymbolAddress((void**)&UTsl, g_UTsl);
    cudaGetSymbolAddress((void**)&wh,   g_wh);    cudaGetSymbolAddress((void**)&wl,   g_wl);
    cudaGetSymbolAddress((void**)&yh,   g_yh);    cudaGetSymbolAddress((void**)&yTh,  g_yTh);
    cudaGetSymbolAddress((void**)&qh,   g_qh);    cudaGetSymbolAddress((void**)&ah,   g_ah);

    cudaFuncSetAttribute(gemm_f16_split,
                         cudaFuncAttributeMaxDynamicSharedMemorySize, GEMM_SMEM);

    const float scale = 1.f / sqrtf((float)DIM);
    const long bnd = (long)SEQ * DIM;   // per-batch stride of x/y slices
    const long smm = (long)SEQ * SEQ;   // one score plane

    // input splits / prep
    k_split<<<(int)((XU_ELEMS/4 + 255)/256), 256>>>(x, xh, xl, XU_ELEMS/4);
    k_split_y_dual<<<dim3(DIM/32, SEQ/32, BATCH), 256>>>(y, yh, yTh);
    k_prep_U<<<dim3(768/32, 768/32), 256>>>(U, S1, S2, UTh, UTl, UTsh, UTsl);
    pos_softmax<<<SEQ, 256>>>(coords, pe, pos);

    // W[h] = (U^T diag(S_h^2)) @ (U^T)^T  -> symmetric 768x768, fp16-split (3-pass)
    gemm_f16_split<<<dim3(768/128, 768/128, 2), 256, GEMM_SMEM>>>(
        UTsh, UTsl, UTh, UTl, nullptr, wh, wl,
        768, 768, 768, 1.f, DD, 0, DD, 3);

    // q[h] = x @ W[h]  (W symmetric; B = W k-major). 2-pass, fp16 hi out.
    gemm_f16_split<<<dim3(768/128, (BATCH*SEQ)/128, 2), 256, GEMM_SMEM>>>(
        xh, xl, wh, wl, nullptr, qh, nullptr,
        BATCH*SEQ, 768, 768, 1.f, 0, DD, XU_ELEMS, 2);

    // G3: scores[b,h] = scale * q[h][b] @ y[b]^T  (batched over b per head, 1-pass)
    gemm_f16_split<<<dim3(SEQ/128, SEQ/128, BATCH), 256, GEMM_SMEM>>>(
        qh,            qh,            yh, yh, attn,       nullptr, nullptr,
        SEQ, SEQ, DIM, scale, bnd, bnd, 2*smm, 1);
    gemm_f16_split<<<dim3(SEQ/128, SEQ/128, BATCH), 256, GEMM_SMEM>>>(
        qh + XU_ELEMS, qh + XU_ELEMS, yh, yh, attn + smm, nullptr, nullptr,
        SEQ, SEQ, DIM, scale, bnd, bnd, 2*smm, 1);

    // fused softmax + mixture + entropy + route + select + heat
    softmax_route_fused<<<BATCH*SEQ, 256>>>(attn, pos, gating, temp, ah,
                                            out + XU_ELEMS);

    // G4: out[b] = attn_sel[b] @ y[b]   (B = y[b]^T k-major over m, 1-pass)
    gemm_f16_split<<<dim3(DIM/128, SEQ/128, BATCH), 256, GEMM_SMEM>>>(
        ah, ah, yTh, yTh, out, nullptr, nullptr,
        SEQ, DIM, SEQ, 1.f, smm, (long)768*1024, bnd, 1);
}

// round 14
// speedup vs baseline: 4.8513x; 1.2170x over previous
#include <cuda_runtime.h>
#include <cuda_fp16.h>
#include <math.h>
#include <stdint.h>

// ----------------------------------------------------------------------------
// Problem constants (B=16, N=M=1024, DIM=768, 2 heads)
// ----------------------------------------------------------------------------
#define BATCH 16
#define SEQ   1024
#define DIM   768
#define XU_ELEMS (16LL*1024*768)        // 12,582,912
#define DD     (768*768)                // 589,824

// ----------------------------------------------------------------------------
// Scratch (static device globals — allocation-free)
// ----------------------------------------------------------------------------
__device__ float g_attn[2LL*16*1024*1024];       // raw scores [B,2,N,M]
__device__ float g_pos [1024LL*1024];            // pos_score [N,M]

// fp16 operands (16B-aligned for cp.async / vector access)
__device__ __align__(16) __half g_xh  [16LL*1024*768];                 // x (hi only)
__device__ __align__(16) __half g_UTh [DD],            g_UTl [DD];
__device__ __align__(16) __half g_UTsh[2*DD],          g_UTsl[2*DD];   // UT*diag(S^2), 2 heads
__device__ __align__(16) __half g_wh  [2*DD];                          // W = U^T diag(S^2) U (hi)
__device__ __align__(16) __half g_yh  [16LL*1024*768];                 // y (hi only)
__device__ __align__(16) __half g_yTh [16LL*768*1024];                 // y^T (hi only)
__device__ __align__(16) __half g_qh  [2LL*16*1024*768];               // x@W per head (hi only)
__device__ __align__(16) __half g_ah  [16LL*1024*1024];                // attn_sel (hi only)

// ----------------------------------------------------------------------------
// PTX helpers (baseline PTX only — valid on compute_103 non-'a')
// ----------------------------------------------------------------------------
__device__ __forceinline__ uint32_t smem_u32(const void* p) {
    uint32_t a;
    asm("{ .reg .u64 t; cvta.to.shared.u64 t, %1; cvt.u32.u64 %0, t; }" : "=r"(a) : "l"(p));
    return a;
}
#define CP_ASYNC16(dst, src) \
    asm volatile("cp.async.cg.shared.global [%0], [%1], 16;" :: "r"(dst), "l"(src))
#define CP_COMMIT() asm volatile("cp.async.commit_group;")
#define CP_WAIT1()  asm volatile("cp.async.wait_group 1;")

#define LDSM_X4(r0, r1, r2, r3, addr) \
    asm volatile("ldmatrix.sync.aligned.m8n8.x4.shared.b16 {%0,%1,%2,%3}, [%4];" \
                 : "=r"(r0), "=r"(r1), "=r"(r2), "=r"(r3) : "r"(addr))

#define MMA16816(d, a, b) \
    asm volatile("mma.sync.aligned.m16n8k16.row.col.f32.f16.f16.f32 " \
                 "{%0,%1,%2,%3}, {%4,%5,%6,%7}, {%8,%9}, {%0,%1,%2,%3};" \
                 : "+f"((d)[0]), "+f"((d)[1]), "+f"((d)[2]), "+f"((d)[3]) \
                 : "r"((a)[0]), "r"((a)[1]), "r"((a)[2]), "r"((a)[3]), \
                   "r"((b)[0]), "r"((b)[1]))

// ----------------------------------------------------------------------------
// fp16 split helpers
// ----------------------------------------------------------------------------
__device__ __forceinline__ uint32_t hpack2(float a, float b) {
    __half ha = __float2half_rn(a), hb = __float2half_rn(b);
    return ((uint32_t)__half_as_ushort(hb) << 16) | (uint32_t)__half_as_ushort(ha);
}
__device__ __forceinline__ uint32_t hpack_hi2(float a, float b, float& ra, float& rb) {
    __half ha = __float2half_rn(a), hb = __float2half_rn(b);
    ra = a - __half2float(ha);
    rb = b - __half2float(hb);
    return ((uint32_t)__half_as_ushort(hb) << 16) | (uint32_t)__half_as_ushort(ha);
}
__device__ __forceinline__ void store_split(__half* H, __half* L, long off, float a, float b) {
    float ra, rb;
    uint32_t hw = hpack_hi2(a, b, ra, rb);
    *(uint32_t*)(H + off) = hw;
    *(uint32_t*)(L + off) = hpack2(ra, rb);
}

// ----------------------------------------------------------------------------
// Pipelined fp16-split GEMM (mma.sync.m16n8k16, HMMA pipe):
//   C[i,j] = alpha * sum_k A[i,k] * B[j,k]
// npass = 3: (Ahi+Alo)@(Bhi) + Ahi@Blo ; npass = 2: (Ahi+Alo)@Bhi ; npass = 1: Ahi@Bhi.
// A: [M,K] k-major, B: [N,K] k-major. M,N mult of 128, K mult of 64.
// Epilogue: Cf -> fp32; else if C1l -> fp16 split (C1h,C1l); else fp16 hi-only C1h.
// CTA 128x128, 8 warps (2x4), warp tile 64x32, 3-stage cp.async pipeline, chunk K=64.
// ----------------------------------------------------------------------------
#define GEMM_SMEM (3 * 32768 + 128)

__global__ __launch_bounds__(256, 2)
void gemm_f16_split(const __half* __restrict__ Ahi, const __half* __restrict__ Alo,
                    const __half* __restrict__ Bhi, const __half* __restrict__ Blo,
                    float* __restrict__ Cf,
                    __half* __restrict__ C1h, __half* __restrict__ C1l,
                    int M, int N, int K, float alpha,
                    long sA, long sB, long sC, int npass)
{
    extern __shared__ char smem_raw[];
    const uint32_t raw_u = smem_u32(smem_raw);
    const uint32_t base  = (raw_u + 127) & ~127u;

    const int tid  = threadIdx.x;
    const int lane = tid & 31;
    const int wid  = tid >> 5;
    const int wm   = wid >> 2;          // 0..1
    const int wn   = wid & 3;           // 0..3

    const int z    = blockIdx.z;
    const int row0 = blockIdx.y * 128;
    const int col0 = blockIdx.x * 128;

    const __half* AP[3] = {Ahi + z * sA, Alo + z * sA, Ahi + z * sA};
    const __half* BP[3] = {Bhi + z * sB, Bhi + z * sB, Blo + z * sB};

    const int kc = K >> 6;              // 64-half chunks per pass
    const int C  = npass * kc;

    // fill assignment: thread covers row r = tid/2, half-row h = tid%2 (32 halfs = 64B)
    const int fr = tid >> 1;
    const int fh = tid & 1;
    const uint32_t fro = (uint32_t)(fr * 128 + fh * 64);

    auto issue = [&](int c) {
        const int s  = c % 3;
        const int p  = c / kc;
        const int kk = (c - p * kc) << 6;
        const __half* ga = AP[p] + (long)(row0 + fr) * K + kk + fh * 32;
        const __half* gb = BP[p] + (long)(col0 + fr) * K + kk + fh * 32;
        const uint32_t sa = base + s * 32768;
        const uint32_t sb = sa + 16384;
        #pragma unroll
        for (int i = 0; i < 4; i++) {
            uint32_t off = fro + i * 16; off ^= (off >> 3) & 0x70;
            CP_ASYNC16(sa + off, ga + i * 8);
        }
        #pragma unroll
        for (int i = 0; i < 4; i++) {
            uint32_t off = fro + i * 16; off ^= (off >> 3) & 0x70;
            CP_ASYNC16(sb + off, gb + i * 8);
        }
        CP_COMMIT();
    };

    float acc[4][4][4] = {};

    issue(0);
    if (C > 1) issue(1);

    for (int c = 0; c < C; c++) {
        CP_WAIT1();
        __syncthreads();
        if (c + 2 < C) issue(c + 2);

        const uint32_t sa = base + (c % 3) * 32768;
        const uint32_t sb = sa + 16384;

        #pragma unroll
        for (int ks = 0; ks < 4; ks++) {
            uint32_t a[4][4];
            #pragma unroll
            for (int mi = 0; mi < 4; mi++) {
                int r  = wm * 64 + mi * 16 + (lane & 15);
                int cb = (ks * 16 + (lane >> 4) * 8) * 2;
                uint32_t off = (uint32_t)(r * 128 + cb); off ^= (off >> 3) & 0x70;
                LDSM_X4(a[mi][0], a[mi][1], a[mi][2], a[mi][3], sa + off);
            }
            uint32_t b[4][2];
            #pragma unroll
            for (int g = 0; g < 2; g++) {
                int n  = wn * 32 + g * 16 + ((lane >> 4) & 1) * 8 + (lane & 7);
                int cb = (ks * 16 + ((lane >> 3) & 1) * 8) * 2;
                uint32_t off = (uint32_t)(n * 128 + cb); off ^= (off >> 3) & 0x70;
                LDSM_X4(b[2*g][0], b[2*g][1], b[2*g+1][0], b[2*g+1][1], sb + off);
            }
            #pragma unroll
            for (int mi = 0; mi < 4; mi++)
                #pragma unroll
                for (int ni = 0; ni < 4; ni++)
                    MMA16816(acc[mi][ni], a[mi], b[ni]);
        }
        __syncthreads();
    }

    // ------------------------------------------------------------------ epilogue
    const long cb0 = (long)z * sC;
    #pragma unroll
    for (int mi = 0; mi < 4; mi++) {
        #pragma unroll
        for (int ni = 0; ni < 4; ni++) {
            const int r  = row0 + wm * 64 + mi * 16 + (lane >> 2);
            const int cc = col0 + wn * 32 + ni * 8 + (lane & 3) * 2;
            const long o0 = cb0 + (long)r * N + cc;
            const long o1 = o0 + 8L * N;
            const float* av = acc[mi][ni];
            if (Cf) {
                *(float2*)(Cf + o0) = make_float2(av[0] * alpha, av[1] * alpha);
                *(float2*)(Cf + o1) = make_float2(av[2] * alpha, av[3] * alpha);
            } else if (C1l) {
                store_split(C1h, C1l, o0, av[0] * alpha, av[1] * alpha);
                store_split(C1h, C1l, o1, av[2] * alpha, av[3] * alpha);
            } else {
                *(uint32_t*)(C1h + o0) = hpack2(av[0] * alpha, av[1] * alpha);
                *(uint32_t*)(C1h + o1) = hpack2(av[2] * alpha, av[3] * alpha);
            }
        }
    }
}

// ----------------------------------------------------------------------------
// Conversion kernels
// ----------------------------------------------------------------------------
// fp32 -> fp16 (hi only)
__global__ void k_cvt(const float* __restrict__ in, __half* __restrict__ hi, long n4)
{
    long i = (long)blockIdx.x * blockDim.x + threadIdx.x;
    if (i >= n4) return;
    float4 v = ((const float4*)in)[i];
    ((uint2*)hi)[i] = make_uint2(hpack2(v.x, v.y), hpack2(v.z, v.w));
}

// y dual convert: read y [SEQ, DIM] once per batch; write straight fp16 (yh)
// and transposed fp16 (yTh [DIM, SEQ]). hi only (lo unused in 1-pass GEMMs).
__global__ void k_split_y_dual(const float* __restrict__ y,
                               __half* __restrict__ yh, __half* __restrict__ yTh)
{
    __shared__ float t[32][33];
    const int z  = blockIdx.z;
    const int c0 = blockIdx.x * 32, r0 = blockIdx.y * 32;
    const float* ip = y + (long)z * SEQ * DIM;
    const int tx = threadIdx.x & 31, ty = threadIdx.x >> 5;
    #pragma unroll
    for (int rr = ty; rr < 32; rr += 8) {
        float v = ip[(long)(r0 + rr) * DIM + c0 + tx];
        t[rr][tx] = v;
        yh[(long)z * SEQ * DIM + (long)(r0 + rr) * DIM + c0 + tx] = __float2half_rn(v);
    }
    __syncthreads();
    #pragma unroll
    for (int cc = ty; cc < 32; cc += 8) {
        float v = t[tx][cc];
        yTh[(long)z * DIM * SEQ + (long)(c0 + cc) * SEQ + r0 + tx] = __float2half_rn(v);
    }
}

// U prep: UT = U^T split, and UTs[h] = U^T * diag(S_h^2) split (both heads).
__global__ void k_prep_U(const float* __restrict__ U,
                         const float* __restrict__ S1, const float* __restrict__ S2,
                         __half* __restrict__ uth, __half* __restrict__ utl,
                         __half* __restrict__ utsh, __half* __restrict__ utsl)
{
    __shared__ float t[32][33];
    const int c0 = blockIdx.x * 32, r0 = blockIdx.y * 32;
    const int tx = threadIdx.x & 31, ty = threadIdx.x >> 5;
    #pragma unroll
    for (int rr = ty; rr < 32; rr += 8)
        t[rr][tx] = U[(long)(r0 + rr) * 768 + c0 + tx];
    __syncthreads();
    const int k = r0 + tx;                       // input row = spectral index
    const float s1 = S1[k], s2 = S2[k];
    const float d1 = s1 * s1, d2 = s2 * s2;
    #pragma unroll
    for (int cc = ty; cc < 32; cc += 8) {
        float v = t[tx][cc];                     // = U[k, c0+cc]
        const long o = (long)(c0 + cc) * 768 + k;
        __half h = __float2half_rn(v);
        uth[o] = h; utl[o] = __float2half_rn(v - __half2float(h));
        float v1 = v * d1;
        __half h1 = __float2half_rn(v1);
        utsh[o] = h1; utsl[o] = __float2half_rn(v1 - __half2float(h1));
        float v2 = v * d2;
        __half h2 = __float2half_rn(v2);
        utsh[DD + o] = h2; utsl[DD + o] = __float2half_rn(v2 - __half2float(h2));
    }
}

// ----------------------------------------------------------------------------
// Block reductions (256 threads, 8 warps)
// ----------------------------------------------------------------------------
__device__ __forceinline__ float block_sum(float v, float* red) {
    #pragma unroll
    for (int o = 16; o; o >>= 1) v += __shfl_xor_sync(0xffffffffu, v, o);
    __syncthreads();
    if ((threadIdx.x & 31) == 0) red[threadIdx.x >> 5] = v;
    __syncthreads();
    float r = red[0];
    #pragma unroll
    for (int w = 1; w < 8; w++) r += red[w];
    return r;
}
__device__ __forceinline__ float block_max(float v, float* red) {
    #pragma unroll
    for (int o = 16; o; o >>= 1) v = fmaxf(v, __shfl_xor_sync(0xffffffffu, v, o));
    __syncthreads();
    if ((threadIdx.x & 31) == 0) red[threadIdx.x >> 5] = v;
    __syncthreads();
    float r = red[0];
    #pragma unroll
    for (int w = 1; w < 8; w++) r = fmaxf(r, red[w]);
    return r;
}

// ----------------------------------------------------------------------------
// pos_score softmax
// ----------------------------------------------------------------------------
__global__ void pos_softmax(const float* __restrict__ coords, const float* __restrict__ pe,
                            float* __restrict__ pos)
{
    const int n   = blockIdx.x;
    const int tid = threadIdx.x;
    __shared__ float red[8];
    __shared__ float w[6];
    if (tid < 6) w[tid] = pe[n * 6 + tid];
    __syncthreads();

    float p[4];
    #pragma unroll
    for (int i = 0; i < 4; i++) {
        const float* c = coords + ((long)n * SEQ + tid * 4 + i) * 6;
        p[i] = w[0]*c[0] + w[1]*c[1] + w[2]*c[2] + w[3]*c[3] + w[4]*c[4] + w[5]*c[5];
    }
    float mx = fmaxf(fmaxf(p[0], p[1]), fmaxf(p[2], p[3]));
    mx = block_max(mx, red);
    float e[4], sum = 0.f;
    #pragma unroll
    for (int i = 0; i < 4; i++) { e[i] = expf(p[i] - mx); sum += e[i]; }
    sum = block_sum(sum, red);
    float inv = 1.f / sum;
    *(float4*)(pos + (long)n * SEQ + tid * 4) = make_float4(e[0]*inv, e[1]*inv, e[2]*inv, e[3]*inv);
}

// ----------------------------------------------------------------------------
// FUSED: softmax + gating mixture + entropy + routing + head-select + fp16.
// One block per (b,n): processes BOTH heads' score rows, routes, and writes
// only the selected attn row (fp16 hi) + heat_map. No fp32 attn writeback.
// ----------------------------------------------------------------------------
__global__ void softmax_route_fused(const float* __restrict__ scores,
                                    const float* __restrict__ pos,
                                    const float* __restrict__ gating,
                                    const float* __restrict__ temp,
                                    __half* __restrict__ ah,
                                    float* __restrict__ heat)
{
    const int r   = blockIdx.x;                 // (b, n)
    const int b   = r >> 10, n = r & 1023;
    const int tid = threadIdx.x;
    __shared__ float red[8];

    const float* row0 = scores + ((long)(b * 2 + 0) * SEQ + n) * SEQ;
    const float* row1 = scores + ((long)(b * 2 + 1) * SEQ + n) * SEQ;
    const float* q    = pos + (long)n * SEQ;

    float4 v0 = *(const float4*)(row0 + tid * 4);
    float4 v1 = *(const float4*)(row1 + tid * 4);
    float4 qv = *(const float4*)(q + tid * 4);

    float mx0 = fmaxf(fmaxf(v0.x, v0.y), fmaxf(v0.z, v0.w));
    float mx1 = fmaxf(fmaxf(v1.x, v1.y), fmaxf(v1.z, v1.w));
    mx0 = block_max(mx0, red);
    mx1 = block_max(mx1, red);

    float4 e0, e1;
    e0.x = expf(v0.x - mx0); e0.y = expf(v0.y - mx0);
    e0.z = expf(v0.z - mx0); e0.w = expf(v0.w - mx0);
    e1.x = expf(v1.x - mx1); e1.y = expf(v1.y - mx1);
    e1.z = expf(v1.z - mx1); e1.w = expf(v1.w - mx1);
    float sum0 = block_sum(e0.x + e0.y + e0.z + e0.w, red);
    float sum1 = block_sum(e1.x + e1.y + e1.z + e1.w, red);

    const float g    = 1.f / (1.f + expf(-gating[0]));
    const float omg0 = (1.f - g) / sum0;
    const float omg1 = (1.f - g) / sum1;

    float4 a0, a1;
    a0.x = omg0*e0.x + g*qv.x; a0.y = omg0*e0.y + g*qv.y;
    a0.z = omg0*e0.z + g*qv.z; a0.w = omg0*e0.w + g*qv.w;
    a1.x = omg1*e1.x + g*qv.x; a1.y = omg1*e1.y + g*qv.y;
    a1.z = omg1*e1.z + g*qv.z; a1.w = omg1*e1.w + g*qv.w;

    float ep0 = -(a0.x * logf(a0.x + 1e-8f) + a0.y * logf(a0.y + 1e-8f)
                + a0.z * logf(a0.z + 1e-8f) + a0.w * logf(a0.w + 1e-8f));
    float ep1 = -(a1.x * logf(a1.x + 1e-8f) + a1.y * logf(a1.y + 1e-8f)
                + a1.z * logf(a1.z + 1e-8f) + a1.w * logf(a1.w + 1e-8f));
    ep0 = block_sum(ep0, red);
    ep1 = block_sum(ep1, red);

    const float t  = temp[0];
    const float h0 = 2.f - 2.f / (1.f + expf(-t * ep0));
    const float h1 = 2.f - 2.f / (1.f + expf(-t * ep1));
    const int   s  = (h0 >= h1) ? 0 : 1;

    if (tid == 0) heat[r] = s ? h1 : h0;

    const float4 a = s ? a1 : a0;
    const long o = (long)r * (SEQ / 4) + tid;
    ((uint2*)ah)[o] = make_uint2(hpack2(a.x, a.y), hpack2(a.z, a.w));
}

// ----------------------------------------------------------------------------
// kernel_launch
// Inputs: 0:x 1:y 2:coords 3:U 4:S1 5:S2 6:gating 7:temp 8:pos_emb
// Output: out [B,N,DIM] (12,582,912 f32) then heat_map [B,N,1] (16,384 f32)
// ----------------------------------------------------------------------------
extern "C" void kernel_launch(void* const* d_in, const int* in_sizes, int n_in,
                              void* d_out, int out_size)
{
    const float* x      = (const float*)d_in[0];
    const float* y      = (const float*)d_in[1];
    const float* coords = (const float*)d_in[2];
    const float* U      = (const float*)d_in[3];
    const float* S1     = (const float*)d_in[4];
    const float* S2     = (const float*)d_in[5];
    const float* gating = (const float*)d_in[6];
    const float* temp   = (const float*)d_in[7];
    const float* pe     = (const float*)d_in[8];
    float* out = (float*)d_out;

    float *attn, *pos;
    __half *xh, *UTh, *UTl, *UTsh, *UTsl, *wh;
    __half *yh, *yTh, *qh, *ah;
    cudaGetSymbolAddress((void**)&attn, g_attn);
    cudaGetSymbolAddress((void**)&pos,  g_pos);
    cudaGetSymbolAddress((void**)&xh,   g_xh);
    cudaGetSymbolAddress((void**)&UTh,  g_UTh);   cudaGetSymbolAddress((void**)&UTl,  g_UTl);
    cudaGetSymbolAddress((void**)&UTsh, g_UTsh);  cudaGetSymbolAddress((void**)&UTsl, g_UTsl);
    cudaGetSymbolAddress((void**)&wh,   g_wh);
    cudaGetSymbolAddress((void**)&yh,   g_yh);    cudaGetSymbolAddress((void**)&yTh,  g_yTh);
    cudaGetSymbolAddress((void**)&qh,   g_qh);    cudaGetSymbolAddress((void**)&ah,   g_ah);

    cudaFuncSetAttribute(gemm_f16_split,
                         cudaFuncAttributeMaxDynamicSharedMemorySize, GEMM_SMEM);

    const float scale = 1.f / sqrtf((float)DIM);
    const long bnd = (long)SEQ * DIM;   // per-batch stride of x/y slices
    const long smm = (long)SEQ * SEQ;   // one score plane

    // input conversions / prep
    k_cvt<<<(int)((XU_ELEMS/4 + 255)/256), 256>>>(x, xh, XU_ELEMS/4);
    k_split_y_dual<<<dim3(DIM/32, SEQ/32, BATCH), 256>>>(y, yh, yTh);
    k_prep_U<<<dim3(768/32, 768/32), 256>>>(U, S1, S2, UTh, UTl, UTsh, UTsl);
    pos_softmax<<<SEQ, 256>>>(coords, pe, pos);

    // W[h] = (U^T diag(S_h^2)) @ (U^T)^T  -> symmetric 768x768, fp16 hi out (3-pass)
    gemm_f16_split<<<dim3(768/128, 768/128, 2), 256, GEMM_SMEM>>>(
        UTsh, UTsl, UTh, UTl, nullptr, wh, nullptr,
        768, 768, 768, 1.f, DD, 0, DD, 3);

    // q[h] = x @ W[h]  (W symmetric; B = W k-major). 1-pass, fp16 hi out.
    gemm_f16_split<<<dim3(768/128, (BATCH*SEQ)/128, 2), 256, GEMM_SMEM>>>(
        xh, xh, wh, wh, nullptr, qh, nullptr,
        BATCH*SEQ, 768, 768, 1.f, 0, DD, XU_ELEMS, 1);

    // G3: scores[b,h] = scale * q[h][b] @ y[b]^T  (batched over b per head, 1-pass)
    gemm_f16_split<<<dim3(SEQ/128, SEQ/128, BATCH), 256, GEMM_SMEM>>>(
        qh,            qh,            yh, yh, attn,       nullptr, nullptr,
        SEQ, SEQ, DIM, scale, bnd, bnd, 2*smm, 1);
    gemm_f16_split<<<dim3(SEQ/128, SEQ/128, BATCH), 256, GEMM_SMEM>>>(
        qh + XU_ELEMS, qh + XU_ELEMS, yh, yh, attn + smm, nullptr, nullptr,
        SEQ, SEQ, DIM, scale, bnd, bnd, 2*smm, 1);

    // fused softmax + mixture + entropy + route + select + heat
    softmax_route_fused<<<BATCH*SEQ, 256>>>(attn, pos, gating, temp, ah,
                                            out + XU_ELEMS);

    // G4: out[b] = attn_sel[b] @ y[b]   (B = y[b]^T k-major over m, 1-pass)
    gemm_f16_split<<<dim3(DIM/128, SEQ/128, BATCH), 256, GEMM_SMEM>>>(
        ah, ah, yTh, yTh, out, nullptr, nullptr,
        SEQ, DIM, SEQ, 1.f, smm, (long)768*1024, bnd, 1);
}